// round 4
// baseline (speedup 1.0000x reference)
#include <cuda_runtime.h>
#include <math.h>

#define NOSC 256
#define DDIM 64
#define NSTEPS 10
#define NTHR 512

typedef unsigned long long u64;

// Transposed W scratch (allowed: __device__ global, no dynamic alloc)
__device__ float g_Wt[NOSC * NOSC];

__global__ void wt_transpose_kernel(const float* __restrict__ W) {
    int j = blockIdx.x;   // 256 blocks
    int i = threadIdx.x;  // 256 threads
    g_Wt[j * NOSC + i] = W[i * NOSC + j];
}

// ---- packed f32x2 helpers (Blackwell FFMA2 path, PTX-only) ----
__device__ __forceinline__ u64 pkd(float a) {            // (a, a)
    u64 r; asm("mov.b64 %0, {%1, %1};" : "=l"(r) : "f"(a)); return r;
}
__device__ __forceinline__ void fma2(u64& d, u64 a, u64 b) {
    asm("fma.rn.f32x2 %0, %1, %2, %0;" : "+l"(d) : "l"(a), "l"(b));
}
__device__ __forceinline__ float2 upk(u64 v) {
    float lo, hi; asm("mov.b64 {%0, %1}, %2;" : "=f"(lo), "=f"(hi) : "l"(v));
    return make_float2(lo, hi);
}

__global__ __launch_bounds__(NTHR, 1)
void akorn_kernel(const float* __restrict__ x_in,
                  const float* __restrict__ eta_p,
                  const float* __restrict__ A,
                  const float* __restrict__ h,
                  const float* __restrict__ w_ro,
                  const float* __restrict__ b_ro,
                  float* __restrict__ out,
                  float* __restrict__ x_out,
                  int write_x)
{
    extern __shared__ float sm[];
    float* xs  = sm;                     // [256][64] oscillator state
    float* Os  = sm + NOSC * DDIM;       // [64][64]  Omega = A - A^T
    float* red = Os + DDIM * DDIM;       // [512] readout reduction

    const int b  = blockIdx.x;
    const int t  = threadIdx.x;
    const int di = t & 7;                // d-group (8 cols each)
    const int ii = t >> 3;               // i-group (4 rows each), 0..63
    const int c0 = di * 8;
    const int r0 = ii * 4;
    const float eta = __ldg(eta_p);

    // Build Omega in smem
    for (int idx = t; idx < DDIM * DDIM; idx += NTHR) {
        int e = idx >> 6, dd = idx & 63;
        Os[idx] = __ldg(&A[e * DDIM + dd]) - __ldg(&A[dd * DDIM + e]);
    }

    // Load + L2-normalize x_b into smem
    const float* xb = x_in + (size_t)b * NOSC * DDIM;
    #pragma unroll
    for (int r = 0; r < 4; r++) {
        int i = r0 + r;
        float4 a0 = __ldg((const float4*)&xb[i * DDIM + c0]);
        float4 a1 = __ldg((const float4*)&xb[i * DDIM + c0 + 4]);
        float ss = a0.x*a0.x + a0.y*a0.y + a0.z*a0.z + a0.w*a0.w
                 + a1.x*a1.x + a1.y*a1.y + a1.z*a1.z + a1.w*a1.w;
        ss += __shfl_xor_sync(0xffffffffu, ss, 1, 8);
        ss += __shfl_xor_sync(0xffffffffu, ss, 2, 8);
        ss += __shfl_xor_sync(0xffffffffu, ss, 4, 8);
        float inv = 1.0f / fmaxf(sqrtf(ss), 1e-12f);
        *(float4*)&xs[i * DDIM + c0] =
            make_float4(a0.x*inv, a0.y*inv, a0.z*inv, a0.w*inv);
        *(float4*)&xs[i * DDIM + c0 + 4] =
            make_float4(a1.x*inv, a1.y*inv, a1.z*inv, a1.w*inv);
    }
    __syncthreads();

    for (int step = 0; step < NSTEPS; step++) {
        // packed accumulators: acc[r][c2] holds (drive[c0+2c2], drive[c0+2c2+1])
        u64 acc[4][4];

        // drive init: h  (memory-natural f32 pairs)
        #pragma unroll
        for (int r = 0; r < 4; r++) {
            int i = r0 + r;
            ulonglong2 h0 = __ldg((const ulonglong2*)&h[i * DDIM + c0]);
            ulonglong2 h1 = __ldg((const ulonglong2*)&h[i * DDIM + c0 + 4]);
            acc[r][0] = h0.x; acc[r][1] = h0.y;
            acc[r][2] = h1.x; acc[r][3] = h1.y;
        }

        // natural frequency rotation: acc[r][*] += xs[i][k] * Omega[k][c0..]
        #pragma unroll 2
        for (int k0 = 0; k0 < DDIM; k0 += 4) {
            u64 op[4][4];
            #pragma unroll
            for (int kk = 0; kk < 4; kk++) {
                ulonglong2 oa = *(const ulonglong2*)&Os[(k0+kk) * DDIM + c0];
                ulonglong2 ob = *(const ulonglong2*)&Os[(k0+kk) * DDIM + c0 + 4];
                op[kk][0] = oa.x; op[kk][1] = oa.y;
                op[kk][2] = ob.x; op[kk][3] = ob.y;
            }
            #pragma unroll
            for (int r = 0; r < 4; r++) {
                float4 xv = *(const float4*)&xs[(r0 + r) * DDIM + k0];
                u64 xd0 = pkd(xv.x), xd1 = pkd(xv.y), xd2 = pkd(xv.z), xd3 = pkd(xv.w);
                #pragma unroll
                for (int c = 0; c < 4; c++) {
                    fma2(acc[r][c], xd0, op[0][c]);
                    fma2(acc[r][c], xd1, op[1][c]);
                    fma2(acc[r][c], xd2, op[2][c]);
                    fma2(acc[r][c], xd3, op[3][c]);
                }
            }
        }

        // coupling: acc[r][*] += W[i][j] * xs[j][c0..]   (W pre-transposed)
        #pragma unroll 4
        for (int j = 0; j < NOSC; j++) {
            float4 w0 = __ldg((const float4*)&g_Wt[j * NOSC + r0]);
            ulonglong2 xq0 = *(const ulonglong2*)&xs[j * DDIM + c0];
            ulonglong2 xq1 = *(const ulonglong2*)&xs[j * DDIM + c0 + 4];
            u64 xp[4] = {xq0.x, xq0.y, xq1.x, xq1.y};
            u64 wd[4] = {pkd(w0.x), pkd(w0.y), pkd(w0.z), pkd(w0.w)};
            #pragma unroll
            for (int r = 0; r < 4; r++) {
                #pragma unroll
                for (int c = 0; c < 4; c++)
                    fma2(acc[r][c], wd[r], xp[c]);
            }
        }

        __syncthreads();  // all cross-thread reads of xs complete

        // tangent-space update + renormalize (thread-private elements only)
        #pragma unroll
        for (int r = 0; r < 4; r++) {
            int i = r0 + r;
            float2 d0 = upk(acc[r][0]), d1 = upk(acc[r][1]);
            float2 d2 = upk(acc[r][2]), d3 = upk(acc[r][3]);
            float dv[8] = {d0.x, d0.y, d1.x, d1.y, d2.x, d2.y, d3.x, d3.y};
            float4 x0 = *(const float4*)&xs[i * DDIM + c0];
            float4 x1 = *(const float4*)&xs[i * DDIM + c0 + 4];
            float xv[8] = {x0.x, x0.y, x0.z, x0.w, x1.x, x1.y, x1.z, x1.w};
            float dp = 0.f;
            #pragma unroll
            for (int c = 0; c < 8; c++) dp += xv[c] * dv[c];
            dp += __shfl_xor_sync(0xffffffffu, dp, 1, 8);
            dp += __shfl_xor_sync(0xffffffffu, dp, 2, 8);
            dp += __shfl_xor_sync(0xffffffffu, dp, 4, 8);
            float nx[8]; float ss = 0.f;
            #pragma unroll
            for (int c = 0; c < 8; c++) {
                nx[c] = xv[c] + eta * (dv[c] - dp * xv[c]);
                ss += nx[c] * nx[c];
            }
            ss += __shfl_xor_sync(0xffffffffu, ss, 1, 8);
            ss += __shfl_xor_sync(0xffffffffu, ss, 2, 8);
            ss += __shfl_xor_sync(0xffffffffu, ss, 4, 8);
            float inv = 1.0f / fmaxf(sqrtf(ss), 1e-12f);
            *(float4*)&xs[i * DDIM + c0] =
                make_float4(nx[0]*inv, nx[1]*inv, nx[2]*inv, nx[3]*inv);
            *(float4*)&xs[i * DDIM + c0 + 4] =
                make_float4(nx[4]*inv, nx[5]*inv, nx[6]*inv, nx[7]*inv);
        }
        __syncthreads();
    }

    // Readout + write final x
    float4 wr0 = __ldg((const float4*)&w_ro[c0]);
    float4 wr1 = __ldg((const float4*)&w_ro[c0 + 4]);
    float wrf[8] = {wr0.x, wr0.y, wr0.z, wr0.w, wr1.x, wr1.y, wr1.z, wr1.w};
    float part = 0.f;
    #pragma unroll
    for (int r = 0; r < 4; r++) {
        int i = r0 + r;
        float4 v0 = *(const float4*)&xs[i * DDIM + c0];
        float4 v1 = *(const float4*)&xs[i * DDIM + c0 + 4];
        part += v0.x*wrf[0] + v0.y*wrf[1] + v0.z*wrf[2] + v0.w*wrf[3]
              + v1.x*wrf[4] + v1.y*wrf[5] + v1.z*wrf[6] + v1.w*wrf[7];
        if (write_x) {
            float* xo = x_out + (size_t)b * NOSC * DDIM + i * DDIM + c0;
            *(float4*)&xo[0] = v0;
            *(float4*)&xo[4] = v1;
        }
    }
    red[t] = part;
    __syncthreads();
    #pragma unroll
    for (int s = NTHR / 2; s > 0; s >>= 1) {
        if (t < s) red[t] += red[t + s];
        __syncthreads();
    }
    if (t == 0) out[b] = red[0] / (float)NOSC + __ldg(b_ro);
}

extern "C" void kernel_launch(void* const* d_in, const int* in_sizes, int n_in,
                              void* d_out, int out_size) {
    const float* x    = (const float*)d_in[0];
    const float* eta  = (const float*)d_in[1];
    const float* W    = (const float*)d_in[2];
    const float* A    = (const float*)d_in[3];
    const float* h    = (const float*)d_in[4];
    const float* w_ro = (const float*)d_in[5];
    const float* b_ro = (const float*)d_in[6];

    const int B = in_sizes[0] / (NOSC * DDIM);
    float* out = (float*)d_out;

    // Output tuple (out, x): out first (B), then x (B*N*d) if the buffer has room.
    int write_x = (out_size >= B + B * NOSC * DDIM) ? 1 : 0;
    float* x_out = out + B;

    const int smem_bytes = (NOSC * DDIM + DDIM * DDIM + NTHR) * (int)sizeof(float);
    cudaFuncSetAttribute(akorn_kernel,
                         cudaFuncAttributeMaxDynamicSharedMemorySize, smem_bytes);

    wt_transpose_kernel<<<NOSC, NOSC>>>(W);
    akorn_kernel<<<B, NTHR, smem_bytes>>>(x, eta, A, h, w_ro, b_ro,
                                          out, x_out, write_x);
}

// round 5
// speedup vs baseline: 1.5341x; 1.5341x over previous
#include <cuda_runtime.h>
#include <math.h>

#define NOSC 256
#define DDIM 64
#define NSTEPS 10

typedef unsigned long long u64;

// Transposed W scratch (allowed: __device__ global, no dynamic alloc)
__device__ float g_Wt[NOSC * NOSC];

__global__ void wt_transpose_kernel(const float* __restrict__ W) {
    int j = blockIdx.x;   // 256 blocks
    int i = threadIdx.x;  // 256 threads
    g_Wt[j * NOSC + i] = W[i * NOSC + j];
}

// ---- packed f32x2 helpers (Blackwell FFMA2 path, PTX-only) ----
__device__ __forceinline__ u64 pkd(float a) {            // (a, a)
    u64 r; asm("mov.b64 %0, {%1, %1};" : "=l"(r) : "f"(a)); return r;
}
__device__ __forceinline__ void fma2(u64& d, u64 a, u64 b) {
    asm("fma.rn.f32x2 %0, %1, %2, %0;" : "+l"(d) : "l"(a), "l"(b));
}
__device__ __forceinline__ float2 upk(u64 v) {
    float lo, hi; asm("mov.b64 {%0, %1}, %2;" : "=f"(lo), "=f"(hi) : "l"(v));
    return make_float2(lo, hi);
}

__global__ __launch_bounds__(256, 2)
void akorn_kernel(const float* __restrict__ x_in,
                  const float* __restrict__ eta_p,
                  const float* __restrict__ A,
                  const float* __restrict__ h,
                  const float* __restrict__ w_ro,
                  const float* __restrict__ b_ro,
                  float* __restrict__ out,
                  float* __restrict__ x_out,
                  int write_x)
{
    extern __shared__ float sm[];
    float* xs  = sm;                     // [256][64] oscillator state
    float* Os  = sm + NOSC * DDIM;       // [64][64]  Omega = A - A^T
    float* red = Os + DDIM * DDIM;       // [256] readout reduction

    const int b  = blockIdx.x;
    const int t  = threadIdx.x;
    const int di = t & 7;                // d-group (8 cols each)
    const int ii = t >> 3;               // i-group (8 rows each), 0..31
    const int c0 = di * 8;
    const float eta = __ldg(eta_p);

    // Build Omega in smem
    for (int idx = t; idx < DDIM * DDIM; idx += 256) {
        int e = idx >> 6, dd = idx & 63;
        Os[idx] = __ldg(&A[e * DDIM + dd]) - __ldg(&A[dd * DDIM + e]);
    }

    // Load + L2-normalize x_b into smem
    const float* xb = x_in + (size_t)b * NOSC * DDIM;
    #pragma unroll
    for (int r = 0; r < 8; r++) {
        int i = ii * 8 + r;
        float4 a0 = __ldg((const float4*)&xb[i * DDIM + c0]);
        float4 a1 = __ldg((const float4*)&xb[i * DDIM + c0 + 4]);
        float ss = a0.x*a0.x + a0.y*a0.y + a0.z*a0.z + a0.w*a0.w
                 + a1.x*a1.x + a1.y*a1.y + a1.z*a1.z + a1.w*a1.w;
        ss += __shfl_xor_sync(0xffffffffu, ss, 1, 8);
        ss += __shfl_xor_sync(0xffffffffu, ss, 2, 8);
        ss += __shfl_xor_sync(0xffffffffu, ss, 4, 8);
        float inv = 1.0f / fmaxf(sqrtf(ss), 1e-12f);
        *(float4*)&xs[i * DDIM + c0] =
            make_float4(a0.x*inv, a0.y*inv, a0.z*inv, a0.w*inv);
        *(float4*)&xs[i * DDIM + c0 + 4] =
            make_float4(a1.x*inv, a1.y*inv, a1.z*inv, a1.w*inv);
    }
    __syncthreads();

    for (int step = 0; step < NSTEPS; step++) {
        // packed accumulators: acc[r][c2] holds (drive[c0+2c2], drive[c0+2c2+1])
        u64 acc[8][4];

        // drive init: h  (memory-natural f32 pairs)
        #pragma unroll
        for (int r = 0; r < 8; r++) {
            int i = ii * 8 + r;
            ulonglong2 h0 = __ldg((const ulonglong2*)&h[i * DDIM + c0]);
            ulonglong2 h1 = __ldg((const ulonglong2*)&h[i * DDIM + c0 + 4]);
            acc[r][0] = h0.x; acc[r][1] = h0.y;
            acc[r][2] = h1.x; acc[r][3] = h1.y;
        }

        // natural frequency rotation: acc[r][*] += xs[i][k] * Omega[k][c0..]
        // k-blocking of 2 keeps live registers low (op[2][4] = 16 regs)
        #pragma unroll 2
        for (int k0 = 0; k0 < DDIM; k0 += 2) {
            u64 op[2][4];
            #pragma unroll
            for (int kk = 0; kk < 2; kk++) {
                ulonglong2 oa = *(const ulonglong2*)&Os[(k0+kk) * DDIM + c0];
                ulonglong2 ob = *(const ulonglong2*)&Os[(k0+kk) * DDIM + c0 + 4];
                op[kk][0] = oa.x; op[kk][1] = oa.y;
                op[kk][2] = ob.x; op[kk][3] = ob.y;
            }
            #pragma unroll
            for (int r = 0; r < 8; r++) {
                float2 xv = *(const float2*)&xs[(ii * 8 + r) * DDIM + k0];
                u64 xd0 = pkd(xv.x), xd1 = pkd(xv.y);
                #pragma unroll
                for (int c = 0; c < 4; c++) {
                    fma2(acc[r][c], xd0, op[0][c]);
                    fma2(acc[r][c], xd1, op[1][c]);
                }
            }
        }

        // coupling: acc[r][*] += W[i][j] * xs[j][c0..]   (W pre-transposed)
        #pragma unroll 2
        for (int j = 0; j < NOSC; j++) {
            float4 w0 = __ldg((const float4*)&g_Wt[j * NOSC + ii * 8]);
            float4 w1 = __ldg((const float4*)&g_Wt[j * NOSC + ii * 8 + 4]);
            ulonglong2 xq0 = *(const ulonglong2*)&xs[j * DDIM + c0];
            ulonglong2 xq1 = *(const ulonglong2*)&xs[j * DDIM + c0 + 4];
            u64 xp[4] = {xq0.x, xq0.y, xq1.x, xq1.y};
            float wf[8] = {w0.x, w0.y, w0.z, w0.w, w1.x, w1.y, w1.z, w1.w};
            #pragma unroll
            for (int r = 0; r < 8; r++) {
                u64 wd = pkd(wf[r]);   // duplicate inline; temp dies immediately
                #pragma unroll
                for (int c = 0; c < 4; c++)
                    fma2(acc[r][c], wd, xp[c]);
            }
        }

        __syncthreads();  // all cross-thread reads of xs complete

        // tangent-space update + renormalize (thread-private elements only)
        #pragma unroll
        for (int r = 0; r < 8; r++) {
            int i = ii * 8 + r;
            float2 d0 = upk(acc[r][0]), d1 = upk(acc[r][1]);
            float2 d2 = upk(acc[r][2]), d3 = upk(acc[r][3]);
            float dv[8] = {d0.x, d0.y, d1.x, d1.y, d2.x, d2.y, d3.x, d3.y};
            float4 x0 = *(const float4*)&xs[i * DDIM + c0];
            float4 x1 = *(const float4*)&xs[i * DDIM + c0 + 4];
            float xv[8] = {x0.x, x0.y, x0.z, x0.w, x1.x, x1.y, x1.z, x1.w};
            float dp = 0.f;
            #pragma unroll
            for (int c = 0; c < 8; c++) dp += xv[c] * dv[c];
            dp += __shfl_xor_sync(0xffffffffu, dp, 1, 8);
            dp += __shfl_xor_sync(0xffffffffu, dp, 2, 8);
            dp += __shfl_xor_sync(0xffffffffu, dp, 4, 8);
            float nx[8]; float ss = 0.f;
            #pragma unroll
            for (int c = 0; c < 8; c++) {
                nx[c] = xv[c] + eta * (dv[c] - dp * xv[c]);
                ss += nx[c] * nx[c];
            }
            ss += __shfl_xor_sync(0xffffffffu, ss, 1, 8);
            ss += __shfl_xor_sync(0xffffffffu, ss, 2, 8);
            ss += __shfl_xor_sync(0xffffffffu, ss, 4, 8);
            float inv = 1.0f / fmaxf(sqrtf(ss), 1e-12f);
            *(float4*)&xs[i * DDIM + c0] =
                make_float4(nx[0]*inv, nx[1]*inv, nx[2]*inv, nx[3]*inv);
            *(float4*)&xs[i * DDIM + c0 + 4] =
                make_float4(nx[4]*inv, nx[5]*inv, nx[6]*inv, nx[7]*inv);
        }
        __syncthreads();
    }

    // Readout + write final x
    float4 wr0 = __ldg((const float4*)&w_ro[c0]);
    float4 wr1 = __ldg((const float4*)&w_ro[c0 + 4]);
    float wrf[8] = {wr0.x, wr0.y, wr0.z, wr0.w, wr1.x, wr1.y, wr1.z, wr1.w};
    float part = 0.f;
    #pragma unroll
    for (int r = 0; r < 8; r++) {
        int i = ii * 8 + r;
        float4 v0 = *(const float4*)&xs[i * DDIM + c0];
        float4 v1 = *(const float4*)&xs[i * DDIM + c0 + 4];
        part += v0.x*wrf[0] + v0.y*wrf[1] + v0.z*wrf[2] + v0.w*wrf[3]
              + v1.x*wrf[4] + v1.y*wrf[5] + v1.z*wrf[6] + v1.w*wrf[7];
        if (write_x) {
            float* xo = x_out + (size_t)b * NOSC * DDIM + i * DDIM + c0;
            *(float4*)&xo[0] = v0;
            *(float4*)&xo[4] = v1;
        }
    }
    red[t] = part;
    __syncthreads();
    #pragma unroll
    for (int s = 128; s > 0; s >>= 1) {
        if (t < s) red[t] += red[t + s];
        __syncthreads();
    }
    if (t == 0) out[b] = red[0] / (float)NOSC + __ldg(b_ro);
}

extern "C" void kernel_launch(void* const* d_in, const int* in_sizes, int n_in,
                              void* d_out, int out_size) {
    const float* x    = (const float*)d_in[0];
    const float* eta  = (const float*)d_in[1];
    const float* W    = (const float*)d_in[2];
    const float* A    = (const float*)d_in[3];
    const float* h    = (const float*)d_in[4];
    const float* w_ro = (const float*)d_in[5];
    const float* b_ro = (const float*)d_in[6];

    const int B = in_sizes[0] / (NOSC * DDIM);
    float* out = (float*)d_out;

    // Output tuple (out, x): out first (B), then x (B*N*d) if the buffer has room.
    int write_x = (out_size >= B + B * NOSC * DDIM) ? 1 : 0;
    float* x_out = out + B;

    const int smem_bytes = (NOSC * DDIM + DDIM * DDIM + 256) * (int)sizeof(float);
    cudaFuncSetAttribute(akorn_kernel,
                         cudaFuncAttributeMaxDynamicSharedMemorySize, smem_bytes);

    wt_transpose_kernel<<<NOSC, NOSC>>>(W);
    akorn_kernel<<<B, 256, smem_bytes>>>(x, eta, A, h, w_ro, b_ro,
                                         out, x_out, write_x);
}

// round 6
// speedup vs baseline: 1.6824x; 1.0967x over previous
#include <cuda_runtime.h>
#include <math.h>

#define NOSC 256
#define DDIM 64
#define NSTEPS 10

typedef unsigned long long u64;

// Transposed W scratch (allowed: __device__ global, no dynamic alloc)
__device__ float g_Wt[NOSC * NOSC];

__global__ void wt_transpose_kernel(const float* __restrict__ W) {
    int j = blockIdx.x;   // 256 blocks
    int i = threadIdx.x;  // 256 threads
    g_Wt[j * NOSC + i] = W[i * NOSC + j];
}

// ---- packed f32x2 helpers (Blackwell FFMA2 path, PTX-only) ----
__device__ __forceinline__ u64 pkd(float a) {            // (a, a)
    u64 r; asm("mov.b64 %0, {%1, %1};" : "=l"(r) : "f"(a)); return r;
}
__device__ __forceinline__ void fma2(u64& d, u64 a, u64 b) {
    asm("fma.rn.f32x2 %0, %1, %2, %0;" : "+l"(d) : "l"(a), "l"(b));
}
__device__ __forceinline__ float2 upk(u64 v) {
    float lo, hi; asm("mov.b64 {%0, %1}, %2;" : "=f"(lo), "=f"(hi) : "l"(v));
    return make_float2(lo, hi);
}

// Conflict-free chunk swizzle within a 64-float row:
// chunk q = c/4 stored at slot (q&1)*8 + (q>>1); word = slot*4 + (c&3).
// Thread di's chunks (2di, 2di+1) -> slots di and 8+di -> 32 banks exactly once.
__device__ __forceinline__ int swz(int c) {
    return (((c >> 2) & 1) << 5) + ((c >> 3) << 2) + (c & 3);
}

__global__ __launch_bounds__(256, 2)
void akorn_kernel(const float* __restrict__ x_in,
                  const float* __restrict__ eta_p,
                  const float* __restrict__ A,
                  const float* __restrict__ h,
                  const float* __restrict__ w_ro,
                  const float* __restrict__ b_ro,
                  float* __restrict__ out,
                  float* __restrict__ x_out,
                  int write_x)
{
    extern __shared__ float sm[];
    float* xs  = sm;                     // [256][64] oscillator state (swizzled rows)
    float* Os  = sm + NOSC * DDIM;       // [64][64]  Omega (swizzled rows)
    float* red = Os + DDIM * DDIM;       // [256] readout reduction

    const int b  = blockIdx.x;
    const int t  = threadIdx.x;
    const int di = t & 7;                // d-group (8 cols each)
    const int ii = t >> 3;               // i-group (8 rows each), 0..31
    const int c0 = di * 8;
    const int sc0 = swz(c0);             // = 4*di
    const int sc1 = swz(c0 + 4);         // = 32 + 4*di
    const float eta = __ldg(eta_p);

    // Build Omega in smem (swizzled)
    for (int idx = t; idx < DDIM * DDIM; idx += 256) {
        int e = idx >> 6, dd = idx & 63;
        Os[e * DDIM + swz(dd)] = __ldg(&A[e * DDIM + dd]) - __ldg(&A[dd * DDIM + e]);
    }

    // Load + L2-normalize x_b into smem (swizzled)
    const float* xb = x_in + (size_t)b * NOSC * DDIM;
    #pragma unroll
    for (int r = 0; r < 8; r++) {
        int i = ii * 8 + r;
        float4 a0 = __ldg((const float4*)&xb[i * DDIM + c0]);
        float4 a1 = __ldg((const float4*)&xb[i * DDIM + c0 + 4]);
        float ss = a0.x*a0.x + a0.y*a0.y + a0.z*a0.z + a0.w*a0.w
                 + a1.x*a1.x + a1.y*a1.y + a1.z*a1.z + a1.w*a1.w;
        ss += __shfl_xor_sync(0xffffffffu, ss, 1, 8);
        ss += __shfl_xor_sync(0xffffffffu, ss, 2, 8);
        ss += __shfl_xor_sync(0xffffffffu, ss, 4, 8);
        float inv = 1.0f / fmaxf(sqrtf(ss), 1e-12f);
        *(float4*)&xs[i * DDIM + sc0] =
            make_float4(a0.x*inv, a0.y*inv, a0.z*inv, a0.w*inv);
        *(float4*)&xs[i * DDIM + sc1] =
            make_float4(a1.x*inv, a1.y*inv, a1.z*inv, a1.w*inv);
    }
    __syncthreads();

    for (int step = 0; step < NSTEPS; step++) {
        // packed accumulators: acc[r][c2] holds (drive[c0+2c2], drive[c0+2c2+1])
        u64 acc[8][4];

        // drive init: h  (memory-natural f32 pairs)
        #pragma unroll
        for (int r = 0; r < 8; r++) {
            int i = ii * 8 + r;
            ulonglong2 h0 = __ldg((const ulonglong2*)&h[i * DDIM + c0]);
            ulonglong2 h1 = __ldg((const ulonglong2*)&h[i * DDIM + c0 + 4]);
            acc[r][0] = h0.x; acc[r][1] = h0.y;
            acc[r][2] = h1.x; acc[r][3] = h1.y;
        }

        // natural frequency rotation: acc[r][*] += xs[i][k] * Omega[k][c0..]
        #pragma unroll 2
        for (int k0 = 0; k0 < DDIM; k0 += 2) {
            u64 op[2][4];
            #pragma unroll
            for (int kk = 0; kk < 2; kk++) {
                ulonglong2 oa = *(const ulonglong2*)&Os[(k0+kk) * DDIM + sc0];
                ulonglong2 ob = *(const ulonglong2*)&Os[(k0+kk) * DDIM + sc1];
                op[kk][0] = oa.x; op[kk][1] = oa.y;
                op[kk][2] = ob.x; op[kk][3] = ob.y;
            }
            const int sk = swz(k0);   // k0 even -> float2 stays inside a chunk
            #pragma unroll
            for (int r = 0; r < 8; r++) {
                float2 xv = *(const float2*)&xs[(ii * 8 + r) * DDIM + sk];
                u64 xd0 = pkd(xv.x), xd1 = pkd(xv.y);
                #pragma unroll
                for (int c = 0; c < 4; c++) {
                    fma2(acc[r][c], xd0, op[0][c]);
                    fma2(acc[r][c], xd1, op[1][c]);
                }
            }
        }

        // coupling: acc[r][*] += W[i][j] * xs[j][c0..]   (W pre-transposed)
        #pragma unroll 2
        for (int j = 0; j < NOSC; j++) {
            float4 w0 = __ldg((const float4*)&g_Wt[j * NOSC + ii * 8]);
            float4 w1 = __ldg((const float4*)&g_Wt[j * NOSC + ii * 8 + 4]);
            ulonglong2 xq0 = *(const ulonglong2*)&xs[j * DDIM + sc0];
            ulonglong2 xq1 = *(const ulonglong2*)&xs[j * DDIM + sc1];
            u64 xp[4] = {xq0.x, xq0.y, xq1.x, xq1.y};
            float wf[8] = {w0.x, w0.y, w0.z, w0.w, w1.x, w1.y, w1.z, w1.w};
            #pragma unroll
            for (int r = 0; r < 8; r++) {
                u64 wd = pkd(wf[r]);   // duplicate inline; temp dies immediately
                #pragma unroll
                for (int c = 0; c < 4; c++)
                    fma2(acc[r][c], wd, xp[c]);
            }
        }

        __syncthreads();  // all cross-thread reads of xs complete

        // tangent-space update + renormalize (thread-private elements only)
        #pragma unroll
        for (int r = 0; r < 8; r++) {
            int i = ii * 8 + r;
            float2 d0 = upk(acc[r][0]), d1 = upk(acc[r][1]);
            float2 d2 = upk(acc[r][2]), d3 = upk(acc[r][3]);
            float dv[8] = {d0.x, d0.y, d1.x, d1.y, d2.x, d2.y, d3.x, d3.y};
            float4 x0 = *(const float4*)&xs[i * DDIM + sc0];
            float4 x1 = *(const float4*)&xs[i * DDIM + sc1];
            float xv[8] = {x0.x, x0.y, x0.z, x0.w, x1.x, x1.y, x1.z, x1.w};
            float dp = 0.f;
            #pragma unroll
            for (int c = 0; c < 8; c++) dp += xv[c] * dv[c];
            dp += __shfl_xor_sync(0xffffffffu, dp, 1, 8);
            dp += __shfl_xor_sync(0xffffffffu, dp, 2, 8);
            dp += __shfl_xor_sync(0xffffffffu, dp, 4, 8);
            float nx[8]; float ss = 0.f;
            #pragma unroll
            for (int c = 0; c < 8; c++) {
                nx[c] = xv[c] + eta * (dv[c] - dp * xv[c]);
                ss += nx[c] * nx[c];
            }
            ss += __shfl_xor_sync(0xffffffffu, ss, 1, 8);
            ss += __shfl_xor_sync(0xffffffffu, ss, 2, 8);
            ss += __shfl_xor_sync(0xffffffffu, ss, 4, 8);
            float inv = 1.0f / fmaxf(sqrtf(ss), 1e-12f);
            *(float4*)&xs[i * DDIM + sc0] =
                make_float4(nx[0]*inv, nx[1]*inv, nx[2]*inv, nx[3]*inv);
            *(float4*)&xs[i * DDIM + sc1] =
                make_float4(nx[4]*inv, nx[5]*inv, nx[6]*inv, nx[7]*inv);
        }
        __syncthreads();
    }

    // Readout + write final x
    float4 wr0 = __ldg((const float4*)&w_ro[c0]);
    float4 wr1 = __ldg((const float4*)&w_ro[c0 + 4]);
    float wrf[8] = {wr0.x, wr0.y, wr0.z, wr0.w, wr1.x, wr1.y, wr1.z, wr1.w};
    float part = 0.f;
    #pragma unroll
    for (int r = 0; r < 8; r++) {
        int i = ii * 8 + r;
        float4 v0 = *(const float4*)&xs[i * DDIM + sc0];
        float4 v1 = *(const float4*)&xs[i * DDIM + sc1];
        part += v0.x*wrf[0] + v0.y*wrf[1] + v0.z*wrf[2] + v0.w*wrf[3]
              + v1.x*wrf[4] + v1.y*wrf[5] + v1.z*wrf[6] + v1.w*wrf[7];
        if (write_x) {
            float* xo = x_out + (size_t)b * NOSC * DDIM + i * DDIM + c0;
            *(float4*)&xo[0] = v0;
            *(float4*)&xo[4] = v1;
        }
    }
    red[t] = part;
    __syncthreads();
    #pragma unroll
    for (int s = 128; s > 0; s >>= 1) {
        if (t < s) red[t] += red[t + s];
        __syncthreads();
    }
    if (t == 0) out[b] = red[0] / (float)NOSC + __ldg(b_ro);
}

extern "C" void kernel_launch(void* const* d_in, const int* in_sizes, int n_in,
                              void* d_out, int out_size) {
    const float* x    = (const float*)d_in[0];
    const float* eta  = (const float*)d_in[1];
    const float* W    = (const float*)d_in[2];
    const float* A    = (const float*)d_in[3];
    const float* h    = (const float*)d_in[4];
    const float* w_ro = (const float*)d_in[5];
    const float* b_ro = (const float*)d_in[6];

    const int B = in_sizes[0] / (NOSC * DDIM);
    float* out = (float*)d_out;

    // Output tuple (out, x): out first (B), then x (B*N*d) if the buffer has room.
    int write_x = (out_size >= B + B * NOSC * DDIM) ? 1 : 0;
    float* x_out = out + B;

    const int smem_bytes = (NOSC * DDIM + DDIM * DDIM + 256) * (int)sizeof(float);
    cudaFuncSetAttribute(akorn_kernel,
                         cudaFuncAttributeMaxDynamicSharedMemorySize, smem_bytes);

    wt_transpose_kernel<<<NOSC, NOSC>>>(W);
    akorn_kernel<<<B, 256, smem_bytes>>>(x, eta, A, h, w_ro, b_ro,
                                         out, x_out, write_x);
}

// round 8
// speedup vs baseline: 3.0972x; 1.8410x over previous
#include <cuda_runtime.h>
#include <cuda_bf16.h>
#include <math.h>

typedef unsigned int u32;
typedef unsigned long long u64;

#define NOSC 256
#define DDIM 64
#define NSTEPS 10
#define XSTR 72            // padded row stride (elems) for X / Omega bf16 buffers
#define WSTR 40            // padded row stride (elems) for W chunks
#define WCHUNK_BYTES 20480 // 256 rows * 40 elems * 2B

// smem byte offsets
#define SM_XHI 0
#define SM_XLO 36864
#define SM_OHI 73728
#define SM_OLO 82944
#define SM_WB0 92160
#define SM_WB1 112640
#define SM_RED 133120
#define SM_TOTAL 134144

// W prepacked: 16 chunks (kc*2 + {hi=0,lo=1}), each the exact smem image (256 x WSTR bf16)
__device__ __nv_bfloat16 g_Wpk[16 * 10240];

__global__ void wprep_kernel(const float* __restrict__ W) {
    int idx = blockIdx.x * 256 + threadIdx.x;   // 65536
    int i = idx >> 8, j = idx & 255;
    float v = W[i * 256 + j];
    __nv_bfloat16 hi = __float2bfloat16(v);
    __nv_bfloat16 lo = __float2bfloat16(v - __bfloat162float(hi));
    int kc = j >> 5, jj = j & 31;
    g_Wpk[(kc * 2 + 0) * 10240 + i * WSTR + jj] = hi;
    g_Wpk[(kc * 2 + 1) * 10240 + i * WSTR + jj] = lo;
}

// ---------------- PTX helpers (all baseline sm_80-level: compile for sm_100) ----------------
__device__ __forceinline__ u32 smem_u32(const void* p) {
    u32 a; asm("{ .reg .u64 t; cvta.to.shared.u64 t, %1; cvt.u32.u64 %0, t; }"
               : "=r"(a) : "l"(p));
    return a;
}
__device__ __forceinline__ void ldsm_x4(u32 addr, u32* r) {
    asm volatile("ldmatrix.sync.aligned.m8n8.x4.shared.b16 {%0,%1,%2,%3}, [%4];"
                 : "=r"(r[0]), "=r"(r[1]), "=r"(r[2]), "=r"(r[3]) : "r"(addr));
}
__device__ __forceinline__ void ldsm_x2t(u32 addr, u32& r0, u32& r1) {
    asm volatile("ldmatrix.sync.aligned.m8n8.x2.trans.shared.b16 {%0,%1}, [%2];"
                 : "=r"(r0), "=r"(r1) : "r"(addr));
}
__device__ __forceinline__ void mma16816(float* c, const u32* a, u32 b0, u32 b1) {
    asm volatile("mma.sync.aligned.m16n8k16.row.col.f32.bf16.bf16.f32 "
                 "{%0,%1,%2,%3}, {%4,%5,%6,%7}, {%8,%9}, {%0,%1,%2,%3};"
                 : "+f"(c[0]), "+f"(c[1]), "+f"(c[2]), "+f"(c[3])
                 : "r"(a[0]), "r"(a[1]), "r"(a[2]), "r"(a[3]), "r"(b0), "r"(b1));
}
#define CP_ASYNC16(dst, src) \
    asm volatile("cp.async.cg.shared.global [%0], [%1], 16;" :: "r"(dst), "l"(src) : "memory")
#define CP_COMMIT()  asm volatile("cp.async.commit_group;" ::: "memory")
#define CP_WAIT1()   asm volatile("cp.async.wait_group 1;" ::: "memory")
#define CP_WAIT0()   asm volatile("cp.async.wait_group 0;" ::: "memory")

__device__ __forceinline__ u32 pack_bf2(float v0, float v1, u32& lo_out) {
    __nv_bfloat16 h0 = __float2bfloat16(v0), h1 = __float2bfloat16(v1);
    __nv_bfloat16 l0 = __float2bfloat16(v0 - __bfloat162float(h0));
    __nv_bfloat16 l1 = __float2bfloat16(v1 - __bfloat162float(h1));
    lo_out = (u32)__bfloat16_as_ushort(l0) | ((u32)__bfloat16_as_ushort(l1) << 16);
    return (u32)__bfloat16_as_ushort(h0) | ((u32)__bfloat16_as_ushort(h1) << 16);
}

__global__ __launch_bounds__(256, 1)
void akorn_kernel(const float* __restrict__ x_in,
                  const float* __restrict__ eta_p,
                  const float* __restrict__ A,
                  const float* __restrict__ h,
                  const float* __restrict__ w_ro,
                  const float* __restrict__ b_ro,
                  float* __restrict__ out,
                  float* __restrict__ x_out,
                  int write_x)
{
    extern __shared__ char smp[];
    const int b = blockIdx.x;
    const int t = threadIdx.x;
    const int wid = t >> 5, lane = t & 31;
    const int g = lane >> 2, tid4 = lane & 3;
    const int lr = lane & 15, lh = lane >> 4;   // ldmatrix row lane / col half
    const int wbase = wid * 32;
    const u32 sb = smem_u32(smp);
    const float eta = __ldg(eta_p);

    // ---- initial x: load row t, normalize, store bf16 hi/lo (padded stride) ----
    {
        const float* xrow = x_in + (size_t)b * NOSC * DDIM + t * DDIM;
        float xr[DDIM]; float ss = 0.f;
        #pragma unroll
        for (int k = 0; k < 16; k++) {
            float4 v = __ldg((const float4*)&xrow[k * 4]);
            xr[4*k] = v.x; xr[4*k+1] = v.y; xr[4*k+2] = v.z; xr[4*k+3] = v.w;
            ss += v.x*v.x + v.y*v.y + v.z*v.z + v.w*v.w;
        }
        float inv = 1.0f / fmaxf(sqrtf(ss), 1e-12f);
        #pragma unroll
        for (int c = 0; c < DDIM; c++) xr[c] *= inv;
        #pragma unroll
        for (int q = 0; q < 8; q++) {
            u32 hs[4], ls[4];
            #pragma unroll
            for (int m = 0; m < 4; m++)
                hs[m] = pack_bf2(xr[q*8 + 2*m], xr[q*8 + 2*m + 1], ls[m]);
            *(uint4*)(smp + SM_XHI + t*144 + q*16) = make_uint4(hs[0], hs[1], hs[2], hs[3]);
            *(uint4*)(smp + SM_XLO + t*144 + q*16) = make_uint4(ls[0], ls[1], ls[2], ls[3]);
        }
    }
    // ---- Omega = A - A^T, bf16 hi/lo ----
    if (t < DDIM) {
        int f = t;
        #pragma unroll 2
        for (int q = 0; q < 8; q++) {
            u32 hs[4], ls[4];
            #pragma unroll
            for (int m = 0; m < 4; m++) {
                int e0 = q*8 + 2*m, e1 = e0 + 1;
                float v0 = __ldg(&A[f * DDIM + e0]) - __ldg(&A[e0 * DDIM + f]);
                float v1 = __ldg(&A[f * DDIM + e1]) - __ldg(&A[e1 * DDIM + f]);
                hs[m] = pack_bf2(v0, v1, ls[m]);
            }
            *(uint4*)(smp + SM_OHI + f*144 + q*16) = make_uint4(hs[0], hs[1], hs[2], hs[3]);
            *(uint4*)(smp + SM_OLO + f*144 + q*16) = make_uint4(ls[0], ls[1], ls[2], ls[3]);
        }
    }
    __syncthreads();

    auto cp_chunk = [&](int p, int buf) {
        u32 sdst = sb + (buf ? SM_WB1 : SM_WB0) + t * 16;
        const char* src = ((const char*)g_Wpk) + (size_t)p * WCHUNK_BYTES + t * 16;
        #pragma unroll
        for (int k2 = 0; k2 < 5; k2++)
            CP_ASYNC16(sdst + k2 * 4096, src + k2 * 4096);
    };

    float part = 0.f;

    for (int step = 0; step < NSTEPS; step++) {
        float C[2][8][4];
        #pragma unroll
        for (int mt = 0; mt < 2; mt++)
            #pragma unroll
            for (int nt = 0; nt < 8; nt++)
                #pragma unroll
                for (int q = 0; q < 4; q++) C[mt][nt][q] = 0.f;

        // start W chunk 0 prefetch, overlap with Omega GEMM
        cp_chunk(0, 0); CP_COMMIT();

        // ---- Omega part: D += Xhi*Ohi + Xhi*Olo + Xlo*Ohi ----
        #pragma unroll
        for (int ks = 0; ks < 4; ks++) {
            const int f0 = ks * 16;
            u32 ah[2][4], al[2][4];
            #pragma unroll
            for (int mt = 0; mt < 2; mt++) {
                u32 arow = (u32)(wbase + mt*16 + lr);
                ldsm_x4(sb + SM_XHI + arow*144 + (u32)(f0 + lh*8)*2, ah[mt]);
                ldsm_x4(sb + SM_XLO + arow*144 + (u32)(f0 + lh*8)*2, al[mt]);
            }
            u32 brow = (u32)(f0 + lr);
            #pragma unroll
            for (int nt = 0; nt < 8; nt++) {
                u32 bh0, bh1, bl0, bl1;
                ldsm_x2t(sb + SM_OHI + brow*144 + nt*16, bh0, bh1);
                ldsm_x2t(sb + SM_OLO + brow*144 + nt*16, bl0, bl1);
                #pragma unroll
                for (int mt = 0; mt < 2; mt++) {
                    mma16816(C[mt][nt], ah[mt], bh0, bh1);
                    mma16816(C[mt][nt], ah[mt], bl0, bl1);
                    mma16816(C[mt][nt], al[mt], bh0, bh1);
                }
            }
        }

        // ---- W part: 16 streamed chunk passes (kc 0..7 x {hi,lo}) ----
        for (int p = 0; p < 16; p++) {
            if (p < 15) { cp_chunk(p + 1, (p + 1) & 1); CP_COMMIT(); CP_WAIT1(); }
            else        { CP_WAIT0(); }
            __syncthreads();
            const u32 wb = sb + ((p & 1) ? SM_WB1 : SM_WB0);
            const int kc = p >> 1, half = p & 1;
            #pragma unroll
            for (int ks = 0; ks < 2; ks++) {
                u32 aw[2][4];
                #pragma unroll
                for (int mt = 0; mt < 2; mt++)
                    ldsm_x4(wb + (u32)(wbase + mt*16 + lr)*80 + (u32)(ks*16 + lh*8)*2, aw[mt]);
                u32 xrb = (u32)(kc*32 + ks*16 + lr) * 144;
                #pragma unroll
                for (int nt = 0; nt < 8; nt++) {
                    u32 b0, b1;
                    ldsm_x2t(sb + SM_XHI + xrb + nt*16, b0, b1);
                    mma16816(C[0][nt], aw[0], b0, b1);
                    mma16816(C[1][nt], aw[1], b0, b1);
                    if (half == 0) {
                        u32 c0, c1;
                        ldsm_x2t(sb + SM_XLO + xrb + nt*16, c0, c1);
                        mma16816(C[0][nt], aw[0], c0, c1);
                        mma16816(C[1][nt], aw[1], c0, c1);
                    }
                }
            }
        }
        __syncthreads();   // all LDSM reads of X done before epilogue rewrites X

        // ---- epilogue in fragment layout ----
        #pragma unroll
        for (int mt = 0; mt < 2; mt++) {
            #pragma unroll
            for (int hh = 0; hh < 2; hh++) {
                const int row = wbase + mt*16 + g + hh*8;
                float xv[16], dvv[16];
                float dot = 0.f;
                #pragma unroll
                for (int nt = 0; nt < 8; nt++) {
                    const int col = nt*8 + tid4*2;
                    float2 hv = *(const float2*)&h[row * DDIM + col];
                    float d0 = C[mt][nt][hh*2 + 0] + hv.x;
                    float d1 = C[mt][nt][hh*2 + 1] + hv.y;
                    u32 off = (u32)row * 144 + (u32)col * 2;
                    u32 vh = *(const u32*)(smp + SM_XHI + off);
                    u32 vl = *(const u32*)(smp + SM_XLO + off);
                    float x0 = __uint_as_float(vh << 16) + __uint_as_float(vl << 16);
                    float x1 = __uint_as_float(vh & 0xffff0000u) + __uint_as_float(vl & 0xffff0000u);
                    dot += x0 * d0 + x1 * d1;
                    xv[nt*2] = x0; xv[nt*2+1] = x1;
                    dvv[nt*2] = d0; dvv[nt*2+1] = d1;
                }
                dot += __shfl_xor_sync(0xffffffffu, dot, 1);
                dot += __shfl_xor_sync(0xffffffffu, dot, 2);
                float ss = 0.f;
                #pragma unroll
                for (int c = 0; c < 16; c++) {
                    xv[c] = xv[c] + eta * (dvv[c] - dot * xv[c]);
                    ss += xv[c] * xv[c];
                }
                ss += __shfl_xor_sync(0xffffffffu, ss, 1);
                ss += __shfl_xor_sync(0xffffffffu, ss, 2);
                float inv = 1.0f / fmaxf(sqrtf(ss), 1e-12f);
                #pragma unroll
                for (int c = 0; c < 16; c++) xv[c] *= inv;
                #pragma unroll
                for (int nt = 0; nt < 8; nt++) {
                    const int col = nt*8 + tid4*2;
                    u32 off = (u32)row * 144 + (u32)col * 2;
                    u32 lo; u32 hi = pack_bf2(xv[nt*2], xv[nt*2+1], lo);
                    *(u32*)(smp + SM_XHI + off) = hi;
                    *(u32*)(smp + SM_XLO + off) = lo;
                }
                if (step == NSTEPS - 1) {
                    #pragma unroll
                    for (int nt = 0; nt < 8; nt++) {
                        const int col = nt*8 + tid4*2;
                        float2 wv = *(const float2*)&w_ro[col];
                        part += xv[nt*2] * wv.x + xv[nt*2+1] * wv.y;
                    }
                    if (write_x) {
                        #pragma unroll
                        for (int nt = 0; nt < 8; nt++) {
                            const int col = nt*8 + tid4*2;
                            *(float2*)&x_out[(size_t)b * NOSC * DDIM + row * DDIM + col] =
                                make_float2(xv[nt*2], xv[nt*2+1]);
                        }
                    }
                }
            }
        }
        __syncthreads();   // new X visible before next step's Omega LDSM
    }

    // ---- readout reduction ----
    float* red = (float*)(smp + SM_RED);
    red[t] = part;
    __syncthreads();
    #pragma unroll
    for (int s = 128; s > 0; s >>= 1) {
        if (t < s) red[t] += red[t + s];
        __syncthreads();
    }
    if (t == 0) out[b] = red[0] / (float)NOSC + __ldg(b_ro);
}

extern "C" void kernel_launch(void* const* d_in, const int* in_sizes, int n_in,
                              void* d_out, int out_size) {
    const float* x    = (const float*)d_in[0];
    const float* eta  = (const float*)d_in[1];
    const float* W    = (const float*)d_in[2];
    const float* A    = (const float*)d_in[3];
    const float* h    = (const float*)d_in[4];
    const float* w_ro = (const float*)d_in[5];
    const float* b_ro = (const float*)d_in[6];

    const int B = in_sizes[0] / (NOSC * DDIM);
    float* out = (float*)d_out;
    int write_x = (out_size >= B + B * NOSC * DDIM) ? 1 : 0;
    float* x_out = out + B;

    cudaFuncSetAttribute(akorn_kernel,
                         cudaFuncAttributeMaxDynamicSharedMemorySize, SM_TOTAL);

    wprep_kernel<<<256, 256>>>(W);
    akorn_kernel<<<B, 256, SM_TOTAL>>>(x, eta, A, h, w_ro, b_ro,
                                       out, x_out, write_x);
}

// round 10
// speedup vs baseline: 4.0581x; 1.3103x over previous
#include <cuda_runtime.h>
#include <cuda_bf16.h>
#include <math.h>

typedef unsigned int u32;

#define NOSC 256
#define DDIM 64
#define NSTEPS 10

// smem byte offsets (total 113 KB -> 2 CTAs/SM)
#define SM_XHI 0
#define SM_XLO 32768
#define SM_OHI 65536
#define SM_OLO 73728
#define SM_WB0 81920
#define SM_WB1 98304
#define SM_RED 114688
#define SM_TOTAL 115712

// W prepacked: 16 chunks (16 j-cols each), chunk = [hl(8192B)][plane(4096B)][row*16B][j*2B]
__device__ __nv_bfloat16 g_Wpk[16 * 8192];

__global__ void wprep_kernel(const float* __restrict__ W) {
    int idx = blockIdx.x * 256 + threadIdx.x;   // 65536
    int i = idx >> 8, j = idx & 255;
    float v = W[i * 256 + j];
    __nv_bfloat16 hi = __float2bfloat16(v);
    __nv_bfloat16 lo = __float2bfloat16(v - __bfloat162float(hi));
    int p = j >> 4, plane = (j >> 3) & 1, jj = j & 7;
    // element offsets: chunk stride 8192, hi/lo stride 4096, plane stride 2048, row stride 8
    g_Wpk[p * 8192 + 0    + plane * 2048 + i * 8 + jj] = hi;
    g_Wpk[p * 8192 + 4096 + plane * 2048 + i * 8 + jj] = lo;
}

// ---------------- PTX helpers (baseline sm_80-level; compile for plain sm_100) ----------------
__device__ __forceinline__ u32 smem_u32(const void* p) {
    u32 a; asm("{ .reg .u64 t; cvta.to.shared.u64 t, %1; cvt.u32.u64 %0, t; }"
               : "=r"(a) : "l"(p));
    return a;
}
__device__ __forceinline__ void ldsm_x4(u32 addr, u32* r) {
    asm volatile("ldmatrix.sync.aligned.m8n8.x4.shared.b16 {%0,%1,%2,%3}, [%4];"
                 : "=r"(r[0]), "=r"(r[1]), "=r"(r[2]), "=r"(r[3]) : "r"(addr));
}
__device__ __forceinline__ void ldsm_x2t(u32 addr, u32& r0, u32& r1) {
    asm volatile("ldmatrix.sync.aligned.m8n8.x2.trans.shared.b16 {%0,%1}, [%2];"
                 : "=r"(r0), "=r"(r1) : "r"(addr));
}
__device__ __forceinline__ void mma16816(float* c, const u32* a, u32 b0, u32 b1) {
    asm volatile("mma.sync.aligned.m16n8k16.row.col.f32.bf16.bf16.f32 "
                 "{%0,%1,%2,%3}, {%4,%5,%6,%7}, {%8,%9}, {%0,%1,%2,%3};"
                 : "+f"(c[0]), "+f"(c[1]), "+f"(c[2]), "+f"(c[3])
                 : "r"(a[0]), "r"(a[1]), "r"(a[2]), "r"(a[3]), "r"(b0), "r"(b1));
}
#define CP_ASYNC16(dst, src) \
    asm volatile("cp.async.cg.shared.global [%0], [%1], 16;" :: "r"(dst), "l"(src) : "memory")
#define CP_COMMIT()  asm volatile("cp.async.commit_group;" ::: "memory")
#define CP_WAIT0()   asm volatile("cp.async.wait_group 0;" ::: "memory")

__device__ __forceinline__ u32 pack_bf2(float v0, float v1, u32& lo_out) {
    __nv_bfloat16 h0 = __float2bfloat16(v0), h1 = __float2bfloat16(v1);
    __nv_bfloat16 l0 = __float2bfloat16(v0 - __bfloat162float(h0));
    __nv_bfloat16 l1 = __float2bfloat16(v1 - __bfloat162float(h1));
    lo_out = (u32)__bfloat16_as_ushort(l0) | ((u32)__bfloat16_as_ushort(l1) << 16);
    return (u32)__bfloat16_as_ushort(h0) | ((u32)__bfloat16_as_ushort(h1) << 16);
}

// XOR chunk swizzle: 128B rows, 16B granules; granule' = granule ^ (row & 7)
__device__ __forceinline__ u32 xaddr(int row, int chunk) {
    return (u32)(row * 128 + ((chunk ^ (row & 7)) << 4));
}

__global__ __launch_bounds__(256, 2)
void akorn_kernel(const float* __restrict__ x_in,
                  const float* __restrict__ eta_p,
                  const float* __restrict__ A,
                  const float* __restrict__ h,
                  const float* __restrict__ w_ro,
                  const float* __restrict__ b_ro,
                  float* __restrict__ out,
                  float* __restrict__ x_out,
                  int write_x)
{
    extern __shared__ char smp[];
    const int b = blockIdx.x;
    const int t = threadIdx.x;
    const int wid = t >> 5, lane = t & 31;
    const int g = lane >> 2, tid4 = lane & 3;
    const int lr = lane & 15, lh = lane >> 4;
    const int wbase = wid * 32;
    const u32 sb = smem_u32(smp);
    const float eta = __ldg(eta_p);

    // ---- initial x: load row t, normalize, store bf16 hi/lo (swizzled) ----
    {
        const float* xrow = x_in + (size_t)b * NOSC * DDIM + t * DDIM;
        float xr[DDIM]; float ss = 0.f;
        #pragma unroll
        for (int k = 0; k < 16; k++) {
            float4 v = __ldg((const float4*)&xrow[k * 4]);
            xr[4*k] = v.x; xr[4*k+1] = v.y; xr[4*k+2] = v.z; xr[4*k+3] = v.w;
            ss += v.x*v.x + v.y*v.y + v.z*v.z + v.w*v.w;
        }
        float inv = 1.0f / fmaxf(sqrtf(ss), 1e-12f);
        #pragma unroll
        for (int c = 0; c < DDIM; c++) xr[c] *= inv;
        #pragma unroll
        for (int q = 0; q < 8; q++) {
            u32 hs[4], ls[4];
            #pragma unroll
            for (int m = 0; m < 4; m++)
                hs[m] = pack_bf2(xr[q*8 + 2*m], xr[q*8 + 2*m + 1], ls[m]);
            u32 a = xaddr(t, q);
            *(uint4*)(smp + SM_XHI + a) = make_uint4(hs[0], hs[1], hs[2], hs[3]);
            *(uint4*)(smp + SM_XLO + a) = make_uint4(ls[0], ls[1], ls[2], ls[3]);
        }
    }
    // ---- Omega = A - A^T, bf16 hi/lo (swizzled) ----
    if (t < DDIM) {
        int f = t;
        #pragma unroll 2
        for (int q = 0; q < 8; q++) {
            u32 hs[4], ls[4];
            #pragma unroll
            for (int m = 0; m < 4; m++) {
                int e0 = q*8 + 2*m, e1 = e0 + 1;
                float v0 = __ldg(&A[f * DDIM + e0]) - __ldg(&A[e0 * DDIM + f]);
                float v1 = __ldg(&A[f * DDIM + e1]) - __ldg(&A[e1 * DDIM + f]);
                hs[m] = pack_bf2(v0, v1, ls[m]);
            }
            u32 a = xaddr(f, q);
            *(uint4*)(smp + SM_OHI + a) = make_uint4(hs[0], hs[1], hs[2], hs[3]);
            *(uint4*)(smp + SM_OLO + a) = make_uint4(ls[0], ls[1], ls[2], ls[3]);
        }
    }
    __syncthreads();

    auto cp_chunk = [&](int p, int buf) {
        u32 sdst = sb + (buf ? SM_WB1 : SM_WB0) + t * 16;
        const char* src = ((const char*)g_Wpk) + (size_t)p * 16384 + t * 16;
        #pragma unroll
        for (int k2 = 0; k2 < 4; k2++)
            CP_ASYNC16(sdst + k2 * 4096, src + k2 * 4096);
    };

    float part = 0.f;

    for (int step = 0; step < NSTEPS; step++) {
        float C[2][8][4];
        #pragma unroll
        for (int mt = 0; mt < 2; mt++)
            #pragma unroll
            for (int nt = 0; nt < 8; nt++)
                #pragma unroll
                for (int q = 0; q < 4; q++) C[mt][nt][q] = 0.f;

        cp_chunk(0, 0); CP_COMMIT();

        // ---- Omega part: D += Xhi*Ohi + Xhi*Olo + Xlo*Ohi ----
        #pragma unroll
        for (int ks = 0; ks < 4; ks++) {
            const int f0 = ks * 16;
            u32 ah[2][4], al[2][4];
            #pragma unroll
            for (int mt = 0; mt < 2; mt++) {
                int arow = wbase + mt*16 + lr;
                u32 aa = xaddr(arow, (f0 >> 3) + lh);
                ldsm_x4(sb + SM_XHI + aa, ah[mt]);
                ldsm_x4(sb + SM_XLO + aa, al[mt]);
            }
            int brow = f0 + lr;
            #pragma unroll
            for (int nt = 0; nt < 8; nt++) {
                u32 ba = xaddr(brow, nt);
                u32 bh0, bh1, bl0, bl1;
                ldsm_x2t(sb + SM_OHI + ba, bh0, bh1);
                ldsm_x2t(sb + SM_OLO + ba, bl0, bl1);
                #pragma unroll
                for (int mt = 0; mt < 2; mt++) {
                    mma16816(C[mt][nt], ah[mt], bh0, bh1);
                    mma16816(C[mt][nt], ah[mt], bl0, bl1);
                    mma16816(C[mt][nt], al[mt], bh0, bh1);
                }
            }
        }

        // ---- W part: 16 streamed passes, 16 j-cols each (hi+lo in one chunk) ----
        for (int p = 0; p < 16; p++) {
            CP_WAIT0();            // chunk p resident
            __syncthreads();       // all warps done with the other buffer (pass p-1)
            if (p < 15) { cp_chunk(p + 1, (p + 1) & 1); CP_COMMIT(); }  // overlaps pass p MMAs
            const u32 wb = sb + ((p & 1) ? SM_WB1 : SM_WB0);
            u32 awh[2][4], awl[2][4];
            #pragma unroll
            for (int mt = 0; mt < 2; mt++) {
                // byte offsets: plane (lh) stride 4096B, lo half at +8192B, row stride 16B
                u32 ra = (u32)((wbase + mt*16 + lr) * 16) + (u32)(lh * 4096);
                ldsm_x4(wb + ra, awh[mt]);
                ldsm_x4(wb + 8192 + ra, awl[mt]);
            }
            int jr = p * 16 + lr;
            #pragma unroll
            for (int nt = 0; nt < 8; nt++) {
                u32 xa = xaddr(jr, nt);
                u32 b0, b1, c0, c1;
                ldsm_x2t(sb + SM_XHI + xa, b0, b1);
                ldsm_x2t(sb + SM_XLO + xa, c0, c1);
                #pragma unroll
                for (int mt = 0; mt < 2; mt++) {
                    mma16816(C[mt][nt], awh[mt], b0, b1);   // Whi * Xhi
                    mma16816(C[mt][nt], awh[mt], c0, c1);   // Whi * Xlo
                    mma16816(C[mt][nt], awl[mt], b0, b1);   // Wlo * Xhi
                }
            }
        }
        __syncthreads();   // all LDSM reads of X done before epilogue rewrites X

        // ---- epilogue in fragment layout ----
        #pragma unroll
        for (int mt = 0; mt < 2; mt++) {
            #pragma unroll
            for (int hh = 0; hh < 2; hh++) {
                const int row = wbase + mt*16 + g + hh*8;
                float xv[16], dvv[16];
                float dot = 0.f;
                #pragma unroll
                for (int nt = 0; nt < 8; nt++) {
                    const int col = nt*8 + tid4*2;
                    float2 hv = *(const float2*)&h[row * DDIM + col];
                    float d0 = C[mt][nt][hh*2 + 0] + hv.x;
                    float d1 = C[mt][nt][hh*2 + 1] + hv.y;
                    u32 off = xaddr(row, nt) + (u32)(tid4 * 4);
                    u32 vh = *(const u32*)(smp + SM_XHI + off);
                    u32 vl = *(const u32*)(smp + SM_XLO + off);
                    float x0 = __uint_as_float(vh << 16) + __uint_as_float(vl << 16);
                    float x1 = __uint_as_float(vh & 0xffff0000u) + __uint_as_float(vl & 0xffff0000u);
                    dot += x0 * d0 + x1 * d1;
                    xv[nt*2] = x0; xv[nt*2+1] = x1;
                    dvv[nt*2] = d0; dvv[nt*2+1] = d1;
                }
                dot += __shfl_xor_sync(0xffffffffu, dot, 1);
                dot += __shfl_xor_sync(0xffffffffu, dot, 2);
                float ss = 0.f;
                #pragma unroll
                for (int c = 0; c < 16; c++) {
                    xv[c] = xv[c] + eta * (dvv[c] - dot * xv[c]);
                    ss += xv[c] * xv[c];
                }
                ss += __shfl_xor_sync(0xffffffffu, ss, 1);
                ss += __shfl_xor_sync(0xffffffffu, ss, 2);
                float inv = 1.0f / fmaxf(sqrtf(ss), 1e-12f);
                #pragma unroll
                for (int c = 0; c < 16; c++) xv[c] *= inv;
                #pragma unroll
                for (int nt = 0; nt < 8; nt++) {
                    u32 off = xaddr(row, nt) + (u32)(tid4 * 4);
                    u32 lo; u32 hi = pack_bf2(xv[nt*2], xv[nt*2+1], lo);
                    *(u32*)(smp + SM_XHI + off) = hi;
                    *(u32*)(smp + SM_XLO + off) = lo;
                }
                if (step == NSTEPS - 1) {
                    #pragma unroll
                    for (int nt = 0; nt < 8; nt++) {
                        const int col = nt*8 + tid4*2;
                        float2 wv = *(const float2*)&w_ro[col];
                        part += xv[nt*2] * wv.x + xv[nt*2+1] * wv.y;
                    }
                    if (write_x) {
                        #pragma unroll
                        for (int nt = 0; nt < 8; nt++) {
                            const int col = nt*8 + tid4*2;
                            *(float2*)&x_out[(size_t)b * NOSC * DDIM + row * DDIM + col] =
                                make_float2(xv[nt*2], xv[nt*2+1]);
                        }
                    }
                }
            }
        }
        __syncthreads();   // new X visible before next step's LDSM
    }

    // ---- readout reduction ----
    float* red = (float*)(smp + SM_RED);
    red[t] = part;
    __syncthreads();
    #pragma unroll
    for (int s = 128; s > 0; s >>= 1) {
        if (t < s) red[t] += red[t + s];
        __syncthreads();
    }
    if (t == 0) out[b] = red[0] / (float)NOSC + __ldg(b_ro);
}

extern "C" void kernel_launch(void* const* d_in, const int* in_sizes, int n_in,
                              void* d_out, int out_size) {
    const float* x    = (const float*)d_in[0];
    const float* eta  = (const float*)d_in[1];
    const float* W    = (const float*)d_in[2];
    const float* A    = (const float*)d_in[3];
    const float* h    = (const float*)d_in[4];
    const float* w_ro = (const float*)d_in[5];
    const float* b_ro = (const float*)d_in[6];

    const int B = in_sizes[0] / (NOSC * DDIM);
    float* out = (float*)d_out;
    int write_x = (out_size >= B + B * NOSC * DDIM) ? 1 : 0;
    float* x_out = out + B;

    cudaFuncSetAttribute(akorn_kernel,
                         cudaFuncAttributeMaxDynamicSharedMemorySize, SM_TOTAL);

    wprep_kernel<<<256, 256>>>(W);
    akorn_kernel<<<B, 256, SM_TOTAL>>>(x, eta, A, h, w_ro, b_ro,
                                       out, x_out, write_x);
}

// round 11
// speedup vs baseline: 5.3744x; 1.3244x over previous
#include <cuda_runtime.h>
#include <cuda_fp16.h>
#include <math.h>

typedef unsigned int u32;

#define NOSC 256
#define DDIM 64
#define NSTEPS 10

// smem byte offsets (total 113 KB -> 2 CTAs/SM)
#define SM_XHI 0
#define SM_XLO 32768
#define SM_OHI 65536
#define SM_OLO 73728
#define SM_WB0 81920
#define SM_WB1 98304
#define SM_RED 114688
#define SM_TOTAL 115712

// W prepacked fp16: 16 chunks (16 j-cols each), chunk = [hl(8192B)][plane(4096B)][row*16B][j*2B]
__device__ __half g_Wpk[16 * 8192];

__global__ void wprep_kernel(const float* __restrict__ W) {
    int idx = blockIdx.x * 256 + threadIdx.x;   // 65536
    int i = idx >> 8, j = idx & 255;
    float v = W[i * 256 + j];
    __half hi = __float2half_rn(v);
    __half lo = __float2half_rn(v - __half2float(hi));
    int p = j >> 4, plane = (j >> 3) & 1, jj = j & 7;
    g_Wpk[p * 8192 + 0    + plane * 2048 + i * 8 + jj] = hi;
    g_Wpk[p * 8192 + 4096 + plane * 2048 + i * 8 + jj] = lo;
}

// ---------------- PTX helpers (baseline sm_80-level; compile for plain sm_100) ----------------
__device__ __forceinline__ u32 smem_u32(const void* p) {
    u32 a; asm("{ .reg .u64 t; cvta.to.shared.u64 t, %1; cvt.u32.u64 %0, t; }"
               : "=r"(a) : "l"(p));
    return a;
}
__device__ __forceinline__ void ldsm_x4(u32 addr, u32* r) {
    asm volatile("ldmatrix.sync.aligned.m8n8.x4.shared.b16 {%0,%1,%2,%3}, [%4];"
                 : "=r"(r[0]), "=r"(r[1]), "=r"(r[2]), "=r"(r[3]) : "r"(addr));
}
__device__ __forceinline__ void ldsm_x2t(u32 addr, u32& r0, u32& r1) {
    asm volatile("ldmatrix.sync.aligned.m8n8.x2.trans.shared.b16 {%0,%1}, [%2];"
                 : "=r"(r0), "=r"(r1) : "r"(addr));
}
__device__ __forceinline__ void mma16816(float* c, const u32* a, u32 b0, u32 b1) {
    asm volatile("mma.sync.aligned.m16n8k16.row.col.f32.f16.f16.f32 "
                 "{%0,%1,%2,%3}, {%4,%5,%6,%7}, {%8,%9}, {%0,%1,%2,%3};"
                 : "+f"(c[0]), "+f"(c[1]), "+f"(c[2]), "+f"(c[3])
                 : "r"(a[0]), "r"(a[1]), "r"(a[2]), "r"(a[3]), "r"(b0), "r"(b1));
}
#define CP_ASYNC16(dst, src) \
    asm volatile("cp.async.cg.shared.global [%0], [%1], 16;" :: "r"(dst), "l"(src) : "memory")
#define CP_COMMIT()  asm volatile("cp.async.commit_group;" ::: "memory")
#define CP_WAIT0()   asm volatile("cp.async.wait_group 0;" ::: "memory")

// fp16 hi/lo pair pack: hi = fp16(v), lo = fp16(v - hi)  (lo may be subnormal: fine)
__device__ __forceinline__ u32 pack_h2(float v0, float v1, u32& lo_out) {
    __half h0 = __float2half_rn(v0), h1 = __float2half_rn(v1);
    __half l0 = __float2half_rn(v0 - __half2float(h0));
    __half l1 = __float2half_rn(v1 - __half2float(h1));
    lo_out = (u32)__half_as_ushort(l0) | ((u32)__half_as_ushort(l1) << 16);
    return (u32)__half_as_ushort(h0) | ((u32)__half_as_ushort(h1) << 16);
}
__device__ __forceinline__ float h2f_lo(u32 v) {
    return __half2float(__ushort_as_half((unsigned short)(v & 0xffffu)));
}
__device__ __forceinline__ float h2f_hi(u32 v) {
    return __half2float(__ushort_as_half((unsigned short)(v >> 16)));
}

// XOR chunk swizzle: 128B rows, 16B granules; granule' = granule ^ (row & 7)
__device__ __forceinline__ u32 xaddr(int row, int chunk) {
    return (u32)(row * 128 + ((chunk ^ (row & 7)) << 4));
}

__global__ __launch_bounds__(256, 2)
void akorn_kernel(const float* __restrict__ x_in,
                  const float* __restrict__ eta_p,
                  const float* __restrict__ A,
                  const float* __restrict__ h,
                  const float* __restrict__ w_ro,
                  const float* __restrict__ b_ro,
                  float* __restrict__ out,
                  float* __restrict__ x_out,
                  int write_x)
{
    extern __shared__ char smp[];
    const int b = blockIdx.x;
    const int t = threadIdx.x;
    const int wid = t >> 5, lane = t & 31;
    const int g = lane >> 2, tid4 = lane & 3;
    const int lr = lane & 15, lh = lane >> 4;
    const int wbase = wid * 32;
    const u32 sb = smem_u32(smp);
    const float eta = __ldg(eta_p);

    // ---- initial x: load row t, normalize, store fp16 hi/lo (swizzled) ----
    {
        const float* xrow = x_in + (size_t)b * NOSC * DDIM + t * DDIM;
        float xr[DDIM]; float ss = 0.f;
        #pragma unroll
        for (int k = 0; k < 16; k++) {
            float4 v = __ldg((const float4*)&xrow[k * 4]);
            xr[4*k] = v.x; xr[4*k+1] = v.y; xr[4*k+2] = v.z; xr[4*k+3] = v.w;
            ss += v.x*v.x + v.y*v.y + v.z*v.z + v.w*v.w;
        }
        float inv = 1.0f / fmaxf(sqrtf(ss), 1e-12f);
        #pragma unroll
        for (int c = 0; c < DDIM; c++) xr[c] *= inv;
        #pragma unroll
        for (int q = 0; q < 8; q++) {
            u32 hs[4], ls[4];
            #pragma unroll
            for (int m = 0; m < 4; m++)
                hs[m] = pack_h2(xr[q*8 + 2*m], xr[q*8 + 2*m + 1], ls[m]);
            u32 a = xaddr(t, q);
            *(uint4*)(smp + SM_XHI + a) = make_uint4(hs[0], hs[1], hs[2], hs[3]);
            *(uint4*)(smp + SM_XLO + a) = make_uint4(ls[0], ls[1], ls[2], ls[3]);
        }
    }
    // ---- Omega = A - A^T, fp16 hi/lo (swizzled) ----
    if (t < DDIM) {
        int f = t;
        #pragma unroll 2
        for (int q = 0; q < 8; q++) {
            u32 hs[4], ls[4];
            #pragma unroll
            for (int m = 0; m < 4; m++) {
                int e0 = q*8 + 2*m, e1 = e0 + 1;
                float v0 = __ldg(&A[f * DDIM + e0]) - __ldg(&A[e0 * DDIM + f]);
                float v1 = __ldg(&A[f * DDIM + e1]) - __ldg(&A[e1 * DDIM + f]);
                hs[m] = pack_h2(v0, v1, ls[m]);
            }
            u32 a = xaddr(f, q);
            *(uint4*)(smp + SM_OHI + a) = make_uint4(hs[0], hs[1], hs[2], hs[3]);
            *(uint4*)(smp + SM_OLO + a) = make_uint4(ls[0], ls[1], ls[2], ls[3]);
        }
    }
    __syncthreads();

    auto cp_chunk = [&](int p, int buf) {
        u32 sdst = sb + (buf ? SM_WB1 : SM_WB0) + t * 16;
        const char* src = ((const char*)g_Wpk) + (size_t)p * 16384 + t * 16;
        #pragma unroll
        for (int k2 = 0; k2 < 4; k2++)
            CP_ASYNC16(sdst + k2 * 4096, src + k2 * 4096);
    };

    float part = 0.f;

    for (int step = 0; step < NSTEPS; step++) {
        float C[2][8][4];
        #pragma unroll
        for (int mt = 0; mt < 2; mt++)
            #pragma unroll
            for (int nt = 0; nt < 8; nt++)
                #pragma unroll
                for (int q = 0; q < 4; q++) C[mt][nt][q] = 0.f;

        cp_chunk(0, 0); CP_COMMIT();

        // ---- Omega part: D += Xhi*(Ohi + Olo)   (2-term fp16) ----
        #pragma unroll
        for (int ks = 0; ks < 4; ks++) {
            const int f0 = ks * 16;
            u32 ah[2][4];
            #pragma unroll
            for (int mt = 0; mt < 2; mt++) {
                int arow = wbase + mt*16 + lr;
                u32 aa = xaddr(arow, (f0 >> 3) + lh);
                ldsm_x4(sb + SM_XHI + aa, ah[mt]);
            }
            int brow = f0 + lr;
            #pragma unroll
            for (int nt = 0; nt < 8; nt++) {
                u32 ba = xaddr(brow, nt);
                u32 bh0, bh1, bl0, bl1;
                ldsm_x2t(sb + SM_OHI + ba, bh0, bh1);
                ldsm_x2t(sb + SM_OLO + ba, bl0, bl1);
                #pragma unroll
                for (int mt = 0; mt < 2; mt++) {
                    mma16816(C[mt][nt], ah[mt], bh0, bh1);
                    mma16816(C[mt][nt], ah[mt], bl0, bl1);
                }
            }
        }

        // ---- W part: 16 streamed passes; D += (Whi + Wlo)*Xhi  (2-term fp16) ----
        for (int p = 0; p < 16; p++) {
            CP_WAIT0();            // chunk p resident
            __syncthreads();       // all warps done with the other buffer (pass p-1)
            if (p < 15) { cp_chunk(p + 1, (p + 1) & 1); CP_COMMIT(); }  // overlaps pass p MMAs
            const u32 wb = sb + ((p & 1) ? SM_WB1 : SM_WB0);
            u32 awh[2][4], awl[2][4];
            #pragma unroll
            for (int mt = 0; mt < 2; mt++) {
                u32 ra = (u32)((wbase + mt*16 + lr) * 16) + (u32)(lh * 4096);
                ldsm_x4(wb + ra, awh[mt]);
                ldsm_x4(wb + 8192 + ra, awl[mt]);
            }
            int jr = p * 16 + lr;
            #pragma unroll
            for (int nt = 0; nt < 8; nt++) {
                u32 xa = xaddr(jr, nt);
                u32 b0, b1;
                ldsm_x2t(sb + SM_XHI + xa, b0, b1);
                #pragma unroll
                for (int mt = 0; mt < 2; mt++) {
                    mma16816(C[mt][nt], awh[mt], b0, b1);   // Whi * Xhi
                    mma16816(C[mt][nt], awl[mt], b0, b1);   // Wlo * Xhi
                }
            }
        }
        __syncthreads();   // all LDSM reads of X done before epilogue rewrites X

        // ---- epilogue in fragment layout (fp32 state = hi + lo) ----
        #pragma unroll
        for (int mt = 0; mt < 2; mt++) {
            #pragma unroll
            for (int hh = 0; hh < 2; hh++) {
                const int row = wbase + mt*16 + g + hh*8;
                float xv[16], dvv[16];
                float dot = 0.f;
                #pragma unroll
                for (int nt = 0; nt < 8; nt++) {
                    const int col = nt*8 + tid4*2;
                    float2 hv = *(const float2*)&h[row * DDIM + col];
                    float d0 = C[mt][nt][hh*2 + 0] + hv.x;
                    float d1 = C[mt][nt][hh*2 + 1] + hv.y;
                    u32 off = xaddr(row, nt) + (u32)(tid4 * 4);
                    u32 vh = *(const u32*)(smp + SM_XHI + off);
                    u32 vl = *(const u32*)(smp + SM_XLO + off);
                    float x0 = h2f_lo(vh) + h2f_lo(vl);
                    float x1 = h2f_hi(vh) + h2f_hi(vl);
                    dot += x0 * d0 + x1 * d1;
                    xv[nt*2] = x0; xv[nt*2+1] = x1;
                    dvv[nt*2] = d0; dvv[nt*2+1] = d1;
                }
                dot += __shfl_xor_sync(0xffffffffu, dot, 1);
                dot += __shfl_xor_sync(0xffffffffu, dot, 2);
                float ss = 0.f;
                #pragma unroll
                for (int c = 0; c < 16; c++) {
                    xv[c] = xv[c] + eta * (dvv[c] - dot * xv[c]);
                    ss += xv[c] * xv[c];
                }
                ss += __shfl_xor_sync(0xffffffffu, ss, 1);
                ss += __shfl_xor_sync(0xffffffffu, ss, 2);
                float inv = 1.0f / fmaxf(sqrtf(ss), 1e-12f);
                #pragma unroll
                for (int c = 0; c < 16; c++) xv[c] *= inv;
                #pragma unroll
                for (int nt = 0; nt < 8; nt++) {
                    u32 off = xaddr(row, nt) + (u32)(tid4 * 4);
                    u32 lo; u32 hi = pack_h2(xv[nt*2], xv[nt*2+1], lo);
                    *(u32*)(smp + SM_XHI + off) = hi;
                    *(u32*)(smp + SM_XLO + off) = lo;
                }
                if (step == NSTEPS - 1) {
                    #pragma unroll
                    for (int nt = 0; nt < 8; nt++) {
                        const int col = nt*8 + tid4*2;
                        float2 wv = *(const float2*)&w_ro[col];
                        part += xv[nt*2] * wv.x + xv[nt*2+1] * wv.y;
                    }
                    if (write_x) {
                        #pragma unroll
                        for (int nt = 0; nt < 8; nt++) {
                            const int col = nt*8 + tid4*2;
                            *(float2*)&x_out[(size_t)b * NOSC * DDIM + row * DDIM + col] =
                                make_float2(xv[nt*2], xv[nt*2+1]);
                        }
                    }
                }
            }
        }
        __syncthreads();   // new X visible before next step's LDSM
    }

    // ---- readout reduction ----
    float* red = (float*)(smp + SM_RED);
    red[t] = part;
    __syncthreads();
    #pragma unroll
    for (int s = 128; s > 0; s >>= 1) {
        if (t < s) red[t] += red[t + s];
        __syncthreads();
    }
    if (t == 0) out[b] = red[0] / (float)NOSC + __ldg(b_ro);
}

extern "C" void kernel_launch(void* const* d_in, const int* in_sizes, int n_in,
                              void* d_out, int out_size) {
    const float* x    = (const float*)d_in[0];
    const float* eta  = (const float*)d_in[1];
    const float* W    = (const float*)d_in[2];
    const float* A    = (const float*)d_in[3];
    const float* h    = (const float*)d_in[4];
    const float* w_ro = (const float*)d_in[5];
    const float* b_ro = (const float*)d_in[6];

    const int B = in_sizes[0] / (NOSC * DDIM);
    float* out = (float*)d_out;
    int write_x = (out_size >= B + B * NOSC * DDIM) ? 1 : 0;
    float* x_out = out + B;

    cudaFuncSetAttribute(akorn_kernel,
                         cudaFuncAttributeMaxDynamicSharedMemorySize, SM_TOTAL);

    wprep_kernel<<<256, 256>>>(W);
    akorn_kernel<<<B, 256, SM_TOTAL>>>(x, eta, A, h, w_ro, b_ro,
                                       out, x_out, write_x);
}

// round 12
// speedup vs baseline: 7.2930x; 1.3570x over previous
#include <cuda_runtime.h>
#include <cuda_fp16.h>
#include <math.h>

typedef unsigned int u32;

#define NOSC 256
#define DDIM 64
#define NSTEPS 10

// smem byte offsets (total 113 KB -> 2 CTAs/SM)
#define SM_XHI 0
#define SM_XLO 32768
#define SM_OHI 65536
#define SM_OLO 73728
#define SM_WB0 81920
#define SM_WB1 98304
#define SM_RED 114688
#define SM_TOTAL 115712

// W prepacked fp16 (hi only): 8 chunks (32 j-cols each), 16 KB/chunk
// chunk layout: [kgroup(8192B)][plane(4096B)][row*16B][j*2B]
__device__ __half g_Wpk[8 * 8192];

__global__ void wprep_kernel(const float* __restrict__ W) {
    int idx = blockIdx.x * 256 + threadIdx.x;   // 65536
    int i = idx >> 8, j = idx & 255;
    float v = W[i * 256 + j];
    __half hi = __float2half_rn(v);
    int p = j >> 5, kg = (j >> 4) & 1, plane = (j >> 3) & 1, jj = j & 7;
    // element offsets: chunk stride 8192, kgroup 4096, plane 2048, row 8
    g_Wpk[p * 8192 + kg * 4096 + plane * 2048 + i * 8 + jj] = hi;
}

// ---------------- PTX helpers (baseline sm_80-level; compile for plain sm_100) ----------------
__device__ __forceinline__ u32 smem_u32(const void* p) {
    u32 a; asm("{ .reg .u64 t; cvta.to.shared.u64 t, %1; cvt.u32.u64 %0, t; }"
               : "=r"(a) : "l"(p));
    return a;
}
__device__ __forceinline__ void ldsm_x4(u32 addr, u32* r) {
    asm volatile("ldmatrix.sync.aligned.m8n8.x4.shared.b16 {%0,%1,%2,%3}, [%4];"
                 : "=r"(r[0]), "=r"(r[1]), "=r"(r[2]), "=r"(r[3]) : "r"(addr));
}
__device__ __forceinline__ void ldsm_x2t(u32 addr, u32& r0, u32& r1) {
    asm volatile("ldmatrix.sync.aligned.m8n8.x2.trans.shared.b16 {%0,%1}, [%2];"
                 : "=r"(r0), "=r"(r1) : "r"(addr));
}
__device__ __forceinline__ void mma16816(float* c, const u32* a, u32 b0, u32 b1) {
    asm volatile("mma.sync.aligned.m16n8k16.row.col.f32.f16.f16.f32 "
                 "{%0,%1,%2,%3}, {%4,%5,%6,%7}, {%8,%9}, {%0,%1,%2,%3};"
                 : "+f"(c[0]), "+f"(c[1]), "+f"(c[2]), "+f"(c[3])
                 : "r"(a[0]), "r"(a[1]), "r"(a[2]), "r"(a[3]), "r"(b0), "r"(b1));
}
#define CP_ASYNC16(dst, src) \
    asm volatile("cp.async.cg.shared.global [%0], [%1], 16;" :: "r"(dst), "l"(src) : "memory")
#define CP_COMMIT()  asm volatile("cp.async.commit_group;" ::: "memory")
#define CP_WAIT0()   asm volatile("cp.async.wait_group 0;" ::: "memory")

// fp16 hi/lo pair pack: hi = fp16(v), lo = fp16(v - hi)  (lo may be subnormal: fine)
__device__ __forceinline__ u32 pack_h2(float v0, float v1, u32& lo_out) {
    __half h0 = __float2half_rn(v0), h1 = __float2half_rn(v1);
    __half l0 = __float2half_rn(v0 - __half2float(h0));
    __half l1 = __float2half_rn(v1 - __half2float(h1));
    lo_out = (u32)__half_as_ushort(l0) | ((u32)__half_as_ushort(l1) << 16);
    return (u32)__half_as_ushort(h0) | ((u32)__half_as_ushort(h1) << 16);
}
__device__ __forceinline__ float h2f_lo(u32 v) {
    return __half2float(__ushort_as_half((unsigned short)(v & 0xffffu)));
}
__device__ __forceinline__ float h2f_hi(u32 v) {
    return __half2float(__ushort_as_half((unsigned short)(v >> 16)));
}

// XOR chunk swizzle: 128B rows, 16B granules; granule' = granule ^ (row & 7)
__device__ __forceinline__ u32 xaddr(int row, int chunk) {
    return (u32)(row * 128 + ((chunk ^ (row & 7)) << 4));
}

__global__ __launch_bounds__(256, 2)
void akorn_kernel(const float* __restrict__ x_in,
                  const float* __restrict__ eta_p,
                  const float* __restrict__ A,
                  const float* __restrict__ h,
                  const float* __restrict__ w_ro,
                  const float* __restrict__ b_ro,
                  float* __restrict__ out,
                  float* __restrict__ x_out,
                  int write_x)
{
    extern __shared__ char smp[];
    const int b = blockIdx.x;
    const int t = threadIdx.x;
    const int wid = t >> 5, lane = t & 31;
    const int g = lane >> 2, tid4 = lane & 3;
    const int lr = lane & 15, lh = lane >> 4;
    const int wbase = wid * 32;
    const u32 sb = smem_u32(smp);
    const float eta = __ldg(eta_p);

    // ---- initial x: load row t, normalize, store fp16 hi/lo (swizzled) ----
    {
        const float* xrow = x_in + (size_t)b * NOSC * DDIM + t * DDIM;
        float xr[DDIM]; float ss = 0.f;
        #pragma unroll
        for (int k = 0; k < 16; k++) {
            float4 v = __ldg((const float4*)&xrow[k * 4]);
            xr[4*k] = v.x; xr[4*k+1] = v.y; xr[4*k+2] = v.z; xr[4*k+3] = v.w;
            ss += v.x*v.x + v.y*v.y + v.z*v.z + v.w*v.w;
        }
        float inv = 1.0f / fmaxf(sqrtf(ss), 1e-12f);
        #pragma unroll
        for (int c = 0; c < DDIM; c++) xr[c] *= inv;
        #pragma unroll
        for (int q = 0; q < 8; q++) {
            u32 hs[4], ls[4];
            #pragma unroll
            for (int m = 0; m < 4; m++)
                hs[m] = pack_h2(xr[q*8 + 2*m], xr[q*8 + 2*m + 1], ls[m]);
            u32 a = xaddr(t, q);
            *(uint4*)(smp + SM_XHI + a) = make_uint4(hs[0], hs[1], hs[2], hs[3]);
            *(uint4*)(smp + SM_XLO + a) = make_uint4(ls[0], ls[1], ls[2], ls[3]);
        }
    }
    // ---- Omega = A - A^T, fp16 hi/lo (swizzled) ----
    if (t < DDIM) {
        int f = t;
        #pragma unroll 2
        for (int q = 0; q < 8; q++) {
            u32 hs[4], ls[4];
            #pragma unroll
            for (int m = 0; m < 4; m++) {
                int e0 = q*8 + 2*m, e1 = e0 + 1;
                float v0 = __ldg(&A[f * DDIM + e0]) - __ldg(&A[e0 * DDIM + f]);
                float v1 = __ldg(&A[f * DDIM + e1]) - __ldg(&A[e1 * DDIM + f]);
                hs[m] = pack_h2(v0, v1, ls[m]);
            }
            u32 a = xaddr(f, q);
            *(uint4*)(smp + SM_OHI + a) = make_uint4(hs[0], hs[1], hs[2], hs[3]);
            *(uint4*)(smp + SM_OLO + a) = make_uint4(ls[0], ls[1], ls[2], ls[3]);
        }
    }
    __syncthreads();

    auto cp_chunk = [&](int p, int buf) {
        u32 sdst = sb + (buf ? SM_WB1 : SM_WB0) + t * 16;
        const char* src = ((const char*)g_Wpk) + (size_t)p * 16384 + t * 16;
        #pragma unroll
        for (int k2 = 0; k2 < 4; k2++)
            CP_ASYNC16(sdst + k2 * 4096, src + k2 * 4096);
    };

    float part = 0.f;

    for (int step = 0; step < NSTEPS; step++) {
        float C[2][8][4];
        #pragma unroll
        for (int mt = 0; mt < 2; mt++)
            #pragma unroll
            for (int nt = 0; nt < 8; nt++)
                #pragma unroll
                for (int q = 0; q < 4; q++) C[mt][nt][q] = 0.f;

        cp_chunk(0, 0); CP_COMMIT();

        // ---- Omega part: D += Xhi*(Ohi + Olo)   (2-term fp16) ----
        #pragma unroll
        for (int ks = 0; ks < 4; ks++) {
            const int f0 = ks * 16;
            u32 ah[2][4];
            #pragma unroll
            for (int mt = 0; mt < 2; mt++) {
                int arow = wbase + mt*16 + lr;
                u32 aa = xaddr(arow, (f0 >> 3) + lh);
                ldsm_x4(sb + SM_XHI + aa, ah[mt]);
            }
            int brow = f0 + lr;
            #pragma unroll
            for (int nt = 0; nt < 8; nt++) {
                u32 ba = xaddr(brow, nt);
                u32 bh0, bh1, bl0, bl1;
                ldsm_x2t(sb + SM_OHI + ba, bh0, bh1);
                ldsm_x2t(sb + SM_OLO + ba, bl0, bl1);
                #pragma unroll
                for (int mt = 0; mt < 2; mt++) {
                    mma16816(C[mt][nt], ah[mt], bh0, bh1);
                    mma16816(C[mt][nt], ah[mt], bl0, bl1);
                }
            }
        }

        // ---- W part: 8 streamed passes of 32 j-cols; D += Whi * Xhi ----
        for (int p = 0; p < 8; p++) {
            CP_WAIT0();            // chunk p resident
            __syncthreads();       // all warps done with the other buffer (pass p-1)
            if (p < 7) { cp_chunk(p + 1, (p + 1) & 1); CP_COMMIT(); }  // overlaps pass p MMAs
            const u32 wb = sb + ((p & 1) ? SM_WB1 : SM_WB0);
            #pragma unroll
            for (int ks = 0; ks < 2; ks++) {
                u32 aw[2][4];
                #pragma unroll
                for (int mt = 0; mt < 2; mt++) {
                    // byte offsets: kgroup (ks) 8192B, plane (lh) 4096B, row 16B
                    u32 ra = (u32)((wbase + mt*16 + lr) * 16) + (u32)(lh * 4096)
                           + (u32)(ks * 8192);
                    ldsm_x4(wb + ra, aw[mt]);
                }
                int jr = p * 32 + ks * 16 + lr;
                #pragma unroll
                for (int nt = 0; nt < 8; nt++) {
                    u32 xa = xaddr(jr, nt);
                    u32 b0, b1;
                    ldsm_x2t(sb + SM_XHI + xa, b0, b1);
                    mma16816(C[0][nt], aw[0], b0, b1);
                    mma16816(C[1][nt], aw[1], b0, b1);
                }
            }
        }
        __syncthreads();   // all LDSM reads of X done before epilogue rewrites X

        // ---- epilogue in fragment layout (fp32 state = hi + lo) ----
        #pragma unroll
        for (int mt = 0; mt < 2; mt++) {
            #pragma unroll
            for (int hh = 0; hh < 2; hh++) {
                const int row = wbase + mt*16 + g + hh*8;
                float xv[16], dvv[16];
                float dot = 0.f;
                #pragma unroll
                for (int nt = 0; nt < 8; nt++) {
                    const int col = nt*8 + tid4*2;
                    float2 hv = *(const float2*)&h[row * DDIM + col];
                    float d0 = C[mt][nt][hh*2 + 0] + hv.x;
                    float d1 = C[mt][nt][hh*2 + 1] + hv.y;
                    u32 off = xaddr(row, nt) + (u32)(tid4 * 4);
                    u32 vh = *(const u32*)(smp + SM_XHI + off);
                    u32 vl = *(const u32*)(smp + SM_XLO + off);
                    float x0 = h2f_lo(vh) + h2f_lo(vl);
                    float x1 = h2f_hi(vh) + h2f_hi(vl);
                    dot += x0 * d0 + x1 * d1;
                    xv[nt*2] = x0; xv[nt*2+1] = x1;
                    dvv[nt*2] = d0; dvv[nt*2+1] = d1;
                }
                dot += __shfl_xor_sync(0xffffffffu, dot, 1);
                dot += __shfl_xor_sync(0xffffffffu, dot, 2);
                float ss = 0.f;
                #pragma unroll
                for (int c = 0; c < 16; c++) {
                    xv[c] = xv[c] + eta * (dvv[c] - dot * xv[c]);
                    ss += xv[c] * xv[c];
                }
                ss += __shfl_xor_sync(0xffffffffu, ss, 1);
                ss += __shfl_xor_sync(0xffffffffu, ss, 2);
                float inv = 1.0f / fmaxf(sqrtf(ss), 1e-12f);
                #pragma unroll
                for (int c = 0; c < 16; c++) xv[c] *= inv;
                #pragma unroll
                for (int nt = 0; nt < 8; nt++) {
                    u32 off = xaddr(row, nt) + (u32)(tid4 * 4);
                    u32 lo; u32 hi = pack_h2(xv[nt*2], xv[nt*2+1], lo);
                    *(u32*)(smp + SM_XHI + off) = hi;
                    *(u32*)(smp + SM_XLO + off) = lo;
                }
                if (step == NSTEPS - 1) {
                    #pragma unroll
                    for (int nt = 0; nt < 8; nt++) {
                        const int col = nt*8 + tid4*2;
                        float2 wv = *(const float2*)&w_ro[col];
                        part += xv[nt*2] * wv.x + xv[nt*2+1] * wv.y;
                    }
                    if (write_x) {
                        #pragma unroll
                        for (int nt = 0; nt < 8; nt++) {
                            const int col = nt*8 + tid4*2;
                            *(float2*)&x_out[(size_t)b * NOSC * DDIM + row * DDIM + col] =
                                make_float2(xv[nt*2], xv[nt*2+1]);
                        }
                    }
                }
            }
        }
        __syncthreads();   // new X visible before next step's LDSM
    }

    // ---- readout reduction ----
    float* red = (float*)(smp + SM_RED);
    red[t] = part;
    __syncthreads();
    #pragma unroll
    for (int s = 128; s > 0; s >>= 1) {
        if (t < s) red[t] += red[t + s];
        __syncthreads();
    }
    if (t == 0) out[b] = red[0] / (float)NOSC + __ldg(b_ro);
}

extern "C" void kernel_launch(void* const* d_in, const int* in_sizes, int n_in,
                              void* d_out, int out_size) {
    const float* x    = (const float*)d_in[0];
    const float* eta  = (const float*)d_in[1];
    const float* W    = (const float*)d_in[2];
    const float* A    = (const float*)d_in[3];
    const float* h    = (const float*)d_in[4];
    const float* w_ro = (const float*)d_in[5];
    const float* b_ro = (const float*)d_in[6];

    const int B = in_sizes[0] / (NOSC * DDIM);
    float* out = (float*)d_out;
    int write_x = (out_size >= B + B * NOSC * DDIM) ? 1 : 0;
    float* x_out = out + B;

    cudaFuncSetAttribute(akorn_kernel,
                         cudaFuncAttributeMaxDynamicSharedMemorySize, SM_TOTAL);

    wprep_kernel<<<256, 256>>>(W);
    akorn_kernel<<<B, 256, SM_TOTAL>>>(x, eta, A, h, w_ro, b_ro,
                                       out, x_out, write_x);
}

// round 13
// speedup vs baseline: 8.2172x; 1.1267x over previous
#include <cuda_runtime.h>
#include <cuda_fp16.h>
#include <math.h>

typedef unsigned int u32;

#define NOSC 256
#define DDIM 64
#define NSTEPS 10

// smem byte offsets (total ~105 KB -> 2 CTAs/SM)
#define SM_XHI 0
#define SM_XLO 32768
#define SM_OHI 65536
#define SM_WB0 73728
#define SM_WB1 90112
#define SM_RED 106496
#define SM_TOTAL 107520

// W prepacked fp16 (hi only): 8 chunks (32 j-cols each), 16 KB/chunk
// chunk layout: [kgroup(8192B)][plane(4096B)][row*16B][j*2B]
__device__ __half g_Wpk[8 * 8192];

__global__ void wprep_kernel(const float* __restrict__ W) {
    int idx = blockIdx.x * 256 + threadIdx.x;   // 65536
    int i = idx >> 8, j = idx & 255;
    float v = W[i * 256 + j];
    __half hi = __float2half_rn(v);
    int p = j >> 5, kg = (j >> 4) & 1, plane = (j >> 3) & 1, jj = j & 7;
    g_Wpk[p * 8192 + kg * 4096 + plane * 2048 + i * 8 + jj] = hi;
}

// ---------------- PTX helpers (baseline sm_80-level; compile for plain sm_100) ----------------
__device__ __forceinline__ u32 smem_u32(const void* p) {
    u32 a; asm("{ .reg .u64 t; cvta.to.shared.u64 t, %1; cvt.u32.u64 %0, t; }"
               : "=r"(a) : "l"(p));
    return a;
}
__device__ __forceinline__ void ldsm_x4(u32 addr, u32* r) {
    asm volatile("ldmatrix.sync.aligned.m8n8.x4.shared.b16 {%0,%1,%2,%3}, [%4];"
                 : "=r"(r[0]), "=r"(r[1]), "=r"(r[2]), "=r"(r[3]) : "r"(addr));
}
// x4 trans: lanes 0-7/8-15 address matrices 0/1 (B frags of nt), 16-23/24-31 matrices 2/3 (nt+1)
__device__ __forceinline__ void ldsm_x4t(u32 addr, u32* r) {
    asm volatile("ldmatrix.sync.aligned.m8n8.x4.trans.shared.b16 {%0,%1,%2,%3}, [%4];"
                 : "=r"(r[0]), "=r"(r[1]), "=r"(r[2]), "=r"(r[3]) : "r"(addr));
}
__device__ __forceinline__ void mma16816(float* c, const u32* a, u32 b0, u32 b1) {
    asm volatile("mma.sync.aligned.m16n8k16.row.col.f32.f16.f16.f32 "
                 "{%0,%1,%2,%3}, {%4,%5,%6,%7}, {%8,%9}, {%0,%1,%2,%3};"
                 : "+f"(c[0]), "+f"(c[1]), "+f"(c[2]), "+f"(c[3])
                 : "r"(a[0]), "r"(a[1]), "r"(a[2]), "r"(a[3]), "r"(b0), "r"(b1));
}
#define CP_ASYNC16(dst, src) \
    asm volatile("cp.async.cg.shared.global [%0], [%1], 16;" :: "r"(dst), "l"(src) : "memory")
#define CP_COMMIT()  asm volatile("cp.async.commit_group;" ::: "memory")
#define CP_WAIT0()   asm volatile("cp.async.wait_group 0;" ::: "memory")

// fp16 hi/lo pair pack: hi = fp16(v), lo = fp16(v - hi)  (lo may be subnormal: fine)
__device__ __forceinline__ u32 pack_h2(float v0, float v1, u32& lo_out) {
    __half h0 = __float2half_rn(v0), h1 = __float2half_rn(v1);
    __half l0 = __float2half_rn(v0 - __half2float(h0));
    __half l1 = __float2half_rn(v1 - __half2float(h1));
    lo_out = (u32)__half_as_ushort(l0) | ((u32)__half_as_ushort(l1) << 16);
    return (u32)__half_as_ushort(h0) | ((u32)__half_as_ushort(h1) << 16);
}
__device__ __forceinline__ float h2f_lo(u32 v) {
    return __half2float(__ushort_as_half((unsigned short)(v & 0xffffu)));
}
__device__ __forceinline__ float h2f_hi(u32 v) {
    return __half2float(__ushort_as_half((unsigned short)(v >> 16)));
}

// XOR chunk swizzle: 128B rows, 16B granules; granule' = granule ^ (row & 7)
__device__ __forceinline__ u32 xaddr(int row, int chunk) {
    return (u32)(row * 128 + ((chunk ^ (row & 7)) << 4));
}

__global__ __launch_bounds__(256, 2)
void akorn_kernel(const float* __restrict__ x_in,
                  const float* __restrict__ eta_p,
                  const float* __restrict__ A,
                  const float* __restrict__ h,
                  const float* __restrict__ w_ro,
                  const float* __restrict__ b_ro,
                  float* __restrict__ out,
                  float* __restrict__ x_out,
                  int write_x)
{
    extern __shared__ char smp[];
    const int b = blockIdx.x;
    const int t = threadIdx.x;
    const int wid = t >> 5, lane = t & 31;
    const int g = lane >> 2, tid4 = lane & 3;
    const int lr = lane & 15, lh = lane >> 4;
    const int l8 = lane & 7, q8 = lane >> 3;      // x4t addressing: q8=0..3
    const int wbase = wid * 32;
    const u32 sb = smem_u32(smp);
    const float eta = __ldg(eta_p);

    // ---- initial x: load row t, normalize, store fp16 hi/lo (swizzled) ----
    {
        const float* xrow = x_in + (size_t)b * NOSC * DDIM + t * DDIM;
        float xr[DDIM]; float ss = 0.f;
        #pragma unroll
        for (int k = 0; k < 16; k++) {
            float4 v = __ldg((const float4*)&xrow[k * 4]);
            xr[4*k] = v.x; xr[4*k+1] = v.y; xr[4*k+2] = v.z; xr[4*k+3] = v.w;
            ss += v.x*v.x + v.y*v.y + v.z*v.z + v.w*v.w;
        }
        float inv = 1.0f / fmaxf(sqrtf(ss), 1e-12f);
        #pragma unroll
        for (int c = 0; c < DDIM; c++) xr[c] *= inv;
        #pragma unroll
        for (int q = 0; q < 8; q++) {
            u32 hs[4], ls[4];
            #pragma unroll
            for (int m = 0; m < 4; m++)
                hs[m] = pack_h2(xr[q*8 + 2*m], xr[q*8 + 2*m + 1], ls[m]);
            u32 a = xaddr(t, q);
            *(uint4*)(smp + SM_XHI + a) = make_uint4(hs[0], hs[1], hs[2], hs[3]);
            *(uint4*)(smp + SM_XLO + a) = make_uint4(ls[0], ls[1], ls[2], ls[3]);
        }
    }
    // ---- Omega = A - A^T, fp16 hi only (swizzled) ----
    if (t < DDIM) {
        int f = t;
        #pragma unroll 2
        for (int q = 0; q < 8; q++) {
            u32 hs[4];
            #pragma unroll
            for (int m = 0; m < 4; m++) {
                int e0 = q*8 + 2*m, e1 = e0 + 1;
                float v0 = __ldg(&A[f * DDIM + e0]) - __ldg(&A[e0 * DDIM + f]);
                float v1 = __ldg(&A[f * DDIM + e1]) - __ldg(&A[e1 * DDIM + f]);
                __half h0 = __float2half_rn(v0), h1 = __float2half_rn(v1);
                hs[m] = (u32)__half_as_ushort(h0) | ((u32)__half_as_ushort(h1) << 16);
            }
            *(uint4*)(smp + SM_OHI + xaddr(f, q)) = make_uint4(hs[0], hs[1], hs[2], hs[3]);
        }
    }
    __syncthreads();

    auto cp_chunk = [&](int p, int buf) {
        u32 sdst = sb + (buf ? SM_WB1 : SM_WB0) + t * 16;
        const char* src = ((const char*)g_Wpk) + (size_t)p * 16384 + t * 16;
        #pragma unroll
        for (int k2 = 0; k2 < 4; k2++)
            CP_ASYNC16(sdst + k2 * 4096, src + k2 * 4096);
    };

    float part = 0.f;

    for (int step = 0; step < NSTEPS; step++) {
        float C[2][8][4];
        #pragma unroll
        for (int mt = 0; mt < 2; mt++)
            #pragma unroll
            for (int nt = 0; nt < 8; nt++)
                #pragma unroll
                for (int q = 0; q < 4; q++) C[mt][nt][q] = 0.f;

        cp_chunk(0, 0); CP_COMMIT();

        // ---- Omega part: D += Xhi * Ohi   (1-term fp16, x4t B loads) ----
        #pragma unroll
        for (int ks = 0; ks < 4; ks++) {
            const int f0 = ks * 16;
            u32 ah[2][4];
            #pragma unroll
            for (int mt = 0; mt < 2; mt++) {
                int arow = wbase + mt*16 + lr;
                ldsm_x4(sb + SM_XHI + xaddr(arow, (f0 >> 3) + lh), ah[mt]);
            }
            // B: x4t loads cover nt2 and nt2+1; lane row = f0 + (q8&1)*8 + l8, chunk = nt2 + (q8>>1)
            #pragma unroll
            for (int nt2 = 0; nt2 < 8; nt2 += 2) {
                u32 bo[4];
                ldsm_x4t(sb + SM_OHI + xaddr(f0 + ((q8 & 1) << 3) + l8, nt2 + (q8 >> 1)), bo);
                #pragma unroll
                for (int mt = 0; mt < 2; mt++) {
                    mma16816(C[mt][nt2],     ah[mt], bo[0], bo[1]);
                    mma16816(C[mt][nt2 + 1], ah[mt], bo[2], bo[3]);
                }
            }
        }

        // ---- W part: 8 streamed passes of 32 j-cols; D += Whi * Xhi (x4t B loads) ----
        for (int p = 0; p < 8; p++) {
            CP_WAIT0();            // chunk p resident
            __syncthreads();       // all warps done with the other buffer (pass p-1)
            if (p < 7) { cp_chunk(p + 1, (p + 1) & 1); CP_COMMIT(); }  // overlaps pass p MMAs
            const u32 wb = sb + ((p & 1) ? SM_WB1 : SM_WB0);
            #pragma unroll
            for (int ks = 0; ks < 2; ks++) {
                u32 aw[2][4];
                #pragma unroll
                for (int mt = 0; mt < 2; mt++) {
                    u32 ra = (u32)((wbase + mt*16 + lr) * 16) + (u32)(lh * 4096)
                           + (u32)(ks * 8192);
                    ldsm_x4(wb + ra, aw[mt]);
                }
                const int jb = p * 32 + ks * 16;
                #pragma unroll
                for (int nt2 = 0; nt2 < 8; nt2 += 2) {
                    u32 bx[4];
                    ldsm_x4t(sb + SM_XHI + xaddr(jb + ((q8 & 1) << 3) + l8, nt2 + (q8 >> 1)), bx);
                    #pragma unroll
                    for (int mt = 0; mt < 2; mt++) {
                        mma16816(C[mt][nt2],     aw[mt], bx[0], bx[1]);
                        mma16816(C[mt][nt2 + 1], aw[mt], bx[2], bx[3]);
                    }
                }
            }
        }
        __syncthreads();   // all LDSM reads of X done before epilogue rewrites X

        // ---- epilogue in fragment layout (fp32 state = hi + lo) ----
        #pragma unroll
        for (int mt = 0; mt < 2; mt++) {
            #pragma unroll
            for (int hh = 0; hh < 2; hh++) {
                const int row = wbase + mt*16 + g + hh*8;
                float xv[16], dvv[16];
                float dot = 0.f;
                #pragma unroll
                for (int nt = 0; nt < 8; nt++) {
                    const int col = nt*8 + tid4*2;
                    float2 hv = *(const float2*)&h[row * DDIM + col];
                    float d0 = C[mt][nt][hh*2 + 0] + hv.x;
                    float d1 = C[mt][nt][hh*2 + 1] + hv.y;
                    u32 off = xaddr(row, nt) + (u32)(tid4 * 4);
                    u32 vh = *(const u32*)(smp + SM_XHI + off);
                    u32 vl = *(const u32*)(smp + SM_XLO + off);
                    float x0 = h2f_lo(vh) + h2f_lo(vl);
                    float x1 = h2f_hi(vh) + h2f_hi(vl);
                    dot += x0 * d0 + x1 * d1;
                    xv[nt*2] = x0; xv[nt*2+1] = x1;
                    dvv[nt*2] = d0; dvv[nt*2+1] = d1;
                }
                dot += __shfl_xor_sync(0xffffffffu, dot, 1);
                dot += __shfl_xor_sync(0xffffffffu, dot, 2);
                float ss = 0.f;
                #pragma unroll
                for (int c = 0; c < 16; c++) {
                    xv[c] = xv[c] + eta * (dvv[c] - dot * xv[c]);
                    ss += xv[c] * xv[c];
                }
                ss += __shfl_xor_sync(0xffffffffu, ss, 1);
                ss += __shfl_xor_sync(0xffffffffu, ss, 2);
                float inv = 1.0f / fmaxf(sqrtf(ss), 1e-12f);
                #pragma unroll
                for (int c = 0; c < 16; c++) xv[c] *= inv;
                #pragma unroll
                for (int nt = 0; nt < 8; nt++) {
                    u32 off = xaddr(row, nt) + (u32)(tid4 * 4);
                    u32 lo; u32 hi = pack_h2(xv[nt*2], xv[nt*2+1], lo);
                    *(u32*)(smp + SM_XHI + off) = hi;
                    *(u32*)(smp + SM_XLO + off) = lo;
                }
                if (step == NSTEPS - 1) {
                    #pragma unroll
                    for (int nt = 0; nt < 8; nt++) {
                        const int col = nt*8 + tid4*2;
                        float2 wv = *(const float2*)&w_ro[col];
                        part += xv[nt*2] * wv.x + xv[nt*2+1] * wv.y;
                    }
                    if (write_x) {
                        #pragma unroll
                        for (int nt = 0; nt < 8; nt++) {
                            const int col = nt*8 + tid4*2;
                            *(float2*)&x_out[(size_t)b * NOSC * DDIM + row * DDIM + col] =
                                make_float2(xv[nt*2], xv[nt*2+1]);
                        }
                    }
                }
            }
        }
        __syncthreads();   // new X visible before next step's LDSM
    }

    // ---- readout reduction ----
    float* red = (float*)(smp + SM_RED);
    red[t] = part;
    __syncthreads();
    #pragma unroll
    for (int s = 128; s > 0; s >>= 1) {
        if (t < s) red[t] += red[t + s];
        __syncthreads();
    }
    if (t == 0) out[b] = red[0] / (float)NOSC + __ldg(b_ro);
}

extern "C" void kernel_launch(void* const* d_in, const int* in_sizes, int n_in,
                              void* d_out, int out_size) {
    const float* x    = (const float*)d_in[0];
    const float* eta  = (const float*)d_in[1];
    const float* W    = (const float*)d_in[2];
    const float* A    = (const float*)d_in[3];
    const float* h    = (const float*)d_in[4];
    const float* w_ro = (const float*)d_in[5];
    const float* b_ro = (const float*)d_in[6];

    const int B = in_sizes[0] / (NOSC * DDIM);
    float* out = (float*)d_out;
    int write_x = (out_size >= B + B * NOSC * DDIM) ? 1 : 0;
    float* x_out = out + B;

    cudaFuncSetAttribute(akorn_kernel,
                         cudaFuncAttributeMaxDynamicSharedMemorySize, SM_TOTAL);

    wprep_kernel<<<256, 256>>>(W);
    akorn_kernel<<<B, 256, SM_TOTAL>>>(x, eta, A, h, w_ro, b_ro,
                                       out, x_out, write_x);
}

// round 14
// speedup vs baseline: 8.5152x; 1.0363x over previous
#include <cuda_runtime.h>
#include <cuda_fp16.h>
#include <math.h>

typedef unsigned int u32;

#define NOSC 256
#define DDIM 64
#define NSTEPS 10

// smem byte offsets (total ~105 KB -> 2 CTAs/SM)
#define SM_XHI 0
#define SM_XLO 32768
#define SM_OHI 65536
#define SM_WB0 73728
#define SM_WB1 90112
#define SM_RED 106496
#define SM_TOTAL 107520

// W prepacked fp16 (hi only), warp-private regions:
// [pass(16384B)][warp(2048B)][kgroup(1024B)][plane(512B)][row*16B][j*2B]
__device__ __half g_Wpk[8 * 8192];

__global__ void wprep_kernel(const float* __restrict__ W) {
    int idx = blockIdx.x * 256 + threadIdx.x;   // 65536
    int i = idx >> 8, j = idx & 255;
    float v = W[i * 256 + j];
    __half hi = __float2half_rn(v);
    int p = j >> 5, ks = (j >> 4) & 1, plane = (j >> 3) & 1, jj = j & 7;
    int w = i >> 5, row = i & 31;
    // element offsets: pass 8192, warp 1024, kgroup 512, plane 256, row 8
    g_Wpk[p * 8192 + w * 1024 + ks * 512 + plane * 256 + row * 8 + jj] = hi;
}

// ---------------- PTX helpers (baseline sm_80-level; compile for plain sm_100) ----------------
__device__ __forceinline__ u32 smem_u32(const void* p) {
    u32 a; asm("{ .reg .u64 t; cvta.to.shared.u64 t, %1; cvt.u32.u64 %0, t; }"
               : "=r"(a) : "l"(p));
    return a;
}
__device__ __forceinline__ void ldsm_x4(u32 addr, u32* r) {
    asm volatile("ldmatrix.sync.aligned.m8n8.x4.shared.b16 {%0,%1,%2,%3}, [%4];"
                 : "=r"(r[0]), "=r"(r[1]), "=r"(r[2]), "=r"(r[3]) : "r"(addr));
}
// x4 trans: lane groups 0-7/8-15/16-23/24-31 address matrices 0/1/2/3
__device__ __forceinline__ void ldsm_x4t(u32 addr, u32* r) {
    asm volatile("ldmatrix.sync.aligned.m8n8.x4.trans.shared.b16 {%0,%1,%2,%3}, [%4];"
                 : "=r"(r[0]), "=r"(r[1]), "=r"(r[2]), "=r"(r[3]) : "r"(addr));
}
__device__ __forceinline__ void mma16816(float* c, const u32* a, u32 b0, u32 b1) {
    asm volatile("mma.sync.aligned.m16n8k16.row.col.f32.f16.f16.f32 "
                 "{%0,%1,%2,%3}, {%4,%5,%6,%7}, {%8,%9}, {%0,%1,%2,%3};"
                 : "+f"(c[0]), "+f"(c[1]), "+f"(c[2]), "+f"(c[3])
                 : "r"(a[0]), "r"(a[1]), "r"(a[2]), "r"(a[3]), "r"(b0), "r"(b1));
}
#define CP_ASYNC16(dst, src) \
    asm volatile("cp.async.cg.shared.global [%0], [%1], 16;" :: "r"(dst), "l"(src) : "memory")
#define CP_COMMIT()  asm volatile("cp.async.commit_group;" ::: "memory")
#define CP_WAIT0()   asm volatile("cp.async.wait_group 0;" ::: "memory")

// fp16 hi/lo pair pack: hi = fp16(v), lo = fp16(v - hi)  (lo may be subnormal: fine)
__device__ __forceinline__ u32 pack_h2(float v0, float v1, u32& lo_out) {
    __half h0 = __float2half_rn(v0), h1 = __float2half_rn(v1);
    __half l0 = __float2half_rn(v0 - __half2float(h0));
    __half l1 = __float2half_rn(v1 - __half2float(h1));
    lo_out = (u32)__half_as_ushort(l0) | ((u32)__half_as_ushort(l1) << 16);
    return (u32)__half_as_ushort(h0) | ((u32)__half_as_ushort(h1) << 16);
}
__device__ __forceinline__ float h2f_lo(u32 v) {
    return __half2float(__ushort_as_half((unsigned short)(v & 0xffffu)));
}
__device__ __forceinline__ float h2f_hi(u32 v) {
    return __half2float(__ushort_as_half((unsigned short)(v >> 16)));
}

// XOR chunk swizzle: 128B rows, 16B granules; granule' = granule ^ (row & 7)
__device__ __forceinline__ u32 xaddr(int row, int chunk) {
    return (u32)(row * 128 + ((chunk ^ (row & 7)) << 4));
}

__global__ __launch_bounds__(256, 2)
void akorn_kernel(const float* __restrict__ x_in,
                  const float* __restrict__ eta_p,
                  const float* __restrict__ A,
                  const float* __restrict__ h,
                  const float* __restrict__ w_ro,
                  const float* __restrict__ b_ro,
                  float* __restrict__ out,
                  float* __restrict__ x_out,
                  int write_x)
{
    extern __shared__ char smp[];
    const int b = blockIdx.x;
    const int t = threadIdx.x;
    const int wid = t >> 5, lane = t & 31;
    const int g = lane >> 2, tid4 = lane & 3;
    const int lr = lane & 15, lh = lane >> 4;
    const int l8 = lane & 7, q8 = lane >> 3;      // x4t addressing
    const int wbase = wid * 32;
    const u32 sb = smem_u32(smp);
    const float eta = __ldg(eta_p);

    // ---- initial x: load row t, normalize, store fp16 hi/lo (swizzled) ----
    {
        const float* xrow = x_in + (size_t)b * NOSC * DDIM + t * DDIM;
        float xr[DDIM]; float ss = 0.f;
        #pragma unroll
        for (int k = 0; k < 16; k++) {
            float4 v = __ldg((const float4*)&xrow[k * 4]);
            xr[4*k] = v.x; xr[4*k+1] = v.y; xr[4*k+2] = v.z; xr[4*k+3] = v.w;
            ss += v.x*v.x + v.y*v.y + v.z*v.z + v.w*v.w;
        }
        float inv = 1.0f / fmaxf(sqrtf(ss), 1e-12f);
        #pragma unroll
        for (int c = 0; c < DDIM; c++) xr[c] *= inv;
        #pragma unroll
        for (int q = 0; q < 8; q++) {
            u32 hs[4], ls[4];
            #pragma unroll
            for (int m = 0; m < 4; m++)
                hs[m] = pack_h2(xr[q*8 + 2*m], xr[q*8 + 2*m + 1], ls[m]);
            u32 a = xaddr(t, q);
            *(uint4*)(smp + SM_XHI + a) = make_uint4(hs[0], hs[1], hs[2], hs[3]);
            *(uint4*)(smp + SM_XLO + a) = make_uint4(ls[0], ls[1], ls[2], ls[3]);
        }
    }
    // ---- Omega = A - A^T, fp16 hi only (swizzled) ----
    if (t < DDIM) {
        int f = t;
        #pragma unroll 2
        for (int q = 0; q < 8; q++) {
            u32 hs[4];
            #pragma unroll
            for (int m = 0; m < 4; m++) {
                int e0 = q*8 + 2*m, e1 = e0 + 1;
                float v0 = __ldg(&A[f * DDIM + e0]) - __ldg(&A[e0 * DDIM + f]);
                float v1 = __ldg(&A[f * DDIM + e1]) - __ldg(&A[e1 * DDIM + f]);
                __half h0 = __float2half_rn(v0), h1 = __float2half_rn(v1);
                hs[m] = (u32)__half_as_ushort(h0) | ((u32)__half_as_ushort(h1) << 16);
            }
            *(uint4*)(smp + SM_OHI + xaddr(f, q)) = make_uint4(hs[0], hs[1], hs[2], hs[3]);
        }
    }
    __syncthreads();

    // Per-warp chunk copy: warp wid copies ONLY its own 2KB region (rows 32*wid..32*wid+31)
    auto cp_chunk = [&](int p, int buf) {
        u32 sdst = sb + (buf ? SM_WB1 : SM_WB0) + (u32)(wid * 2048 + lane * 16);
        const char* src = ((const char*)g_Wpk) + (size_t)p * 16384 + wid * 2048 + lane * 16;
        #pragma unroll
        for (int k2 = 0; k2 < 4; k2++)
            CP_ASYNC16(sdst + k2 * 512, src + k2 * 512);
    };

    float part = 0.f;

    for (int step = 0; step < NSTEPS; step++) {
        float C[2][8][4];
        #pragma unroll
        for (int mt = 0; mt < 2; mt++)
            #pragma unroll
            for (int nt = 0; nt < 8; nt++)
                #pragma unroll
                for (int q = 0; q < 4; q++) C[mt][nt][q] = 0.f;

        cp_chunk(0, 0); CP_COMMIT();

        // ---- Omega part: D += Xhi * Ohi   (1-term fp16, x4t B loads) ----
        #pragma unroll
        for (int ks = 0; ks < 4; ks++) {
            const int f0 = ks * 16;
            u32 ah[2][4];
            #pragma unroll
            for (int mt = 0; mt < 2; mt++) {
                int arow = wbase + mt*16 + lr;
                ldsm_x4(sb + SM_XHI + xaddr(arow, (f0 >> 3) + lh), ah[mt]);
            }
            #pragma unroll
            for (int nt2 = 0; nt2 < 8; nt2 += 2) {
                u32 bo[4];
                ldsm_x4t(sb + SM_OHI + xaddr(f0 + ((q8 & 1) << 3) + l8, nt2 + (q8 >> 1)), bo);
                #pragma unroll
                for (int mt = 0; mt < 2; mt++) {
                    mma16816(C[mt][nt2],     ah[mt], bo[0], bo[1]);
                    mma16816(C[mt][nt2 + 1], ah[mt], bo[2], bo[3]);
                }
            }
        }

        // ---- W part: 8 warp-asynchronous passes of 32 j-cols; D += Whi * Xhi ----
        // No block barriers: each warp gates only on its OWN cp.async group;
        // X is read-only throughout, W regions are warp-private.
        for (int p = 0; p < 8; p++) {
            CP_WAIT0();                                       // own region of chunk p resident
            if (p < 7) { cp_chunk(p + 1, (p + 1) & 1); CP_COMMIT(); }
            const u32 wb = sb + ((p & 1) ? SM_WB1 : SM_WB0) + (u32)(wid * 2048);
            #pragma unroll
            for (int ks = 0; ks < 2; ks++) {
                u32 aw[2][4];
                #pragma unroll
                for (int mt = 0; mt < 2; mt++) {
                    // byte offsets within warp region: kgroup 1024B, plane (lh) 512B, row 16B
                    u32 ra = (u32)(ks * 1024 + lh * 512 + (mt*16 + lr) * 16);
                    ldsm_x4(wb + ra, aw[mt]);
                }
                const int jb = p * 32 + ks * 16;
                #pragma unroll
                for (int nt2 = 0; nt2 < 8; nt2 += 2) {
                    u32 bx[4];
                    ldsm_x4t(sb + SM_XHI + xaddr(jb + ((q8 & 1) << 3) + l8, nt2 + (q8 >> 1)), bx);
                    #pragma unroll
                    for (int mt = 0; mt < 2; mt++) {
                        mma16816(C[mt][nt2],     aw[mt], bx[0], bx[1]);
                        mma16816(C[mt][nt2 + 1], aw[mt], bx[2], bx[3]);
                    }
                }
            }
        }
        __syncthreads();   // all warps' LDSM reads of X done before epilogue rewrites X

        // ---- epilogue in fragment layout (fp32 state = hi + lo) ----
        #pragma unroll
        for (int mt = 0; mt < 2; mt++) {
            #pragma unroll
            for (int hh = 0; hh < 2; hh++) {
                const int row = wbase + mt*16 + g + hh*8;
                float xv[16], dvv[16];
                float dot = 0.f;
                #pragma unroll
                for (int nt = 0; nt < 8; nt++) {
                    const int col = nt*8 + tid4*2;
                    float2 hv = *(const float2*)&h[row * DDIM + col];
                    float d0 = C[mt][nt][hh*2 + 0] + hv.x;
                    float d1 = C[mt][nt][hh*2 + 1] + hv.y;
                    u32 off = xaddr(row, nt) + (u32)(tid4 * 4);
                    u32 vh = *(const u32*)(smp + SM_XHI + off);
                    u32 vl = *(const u32*)(smp + SM_XLO + off);
                    float x0 = h2f_lo(vh) + h2f_lo(vl);
                    float x1 = h2f_hi(vh) + h2f_hi(vl);
                    dot += x0 * d0 + x1 * d1;
                    xv[nt*2] = x0; xv[nt*2+1] = x1;
                    dvv[nt*2] = d0; dvv[nt*2+1] = d1;
                }
                dot += __shfl_xor_sync(0xffffffffu, dot, 1);
                dot += __shfl_xor_sync(0xffffffffu, dot, 2);
                float ss = 0.f;
                #pragma unroll
                for (int c = 0; c < 16; c++) {
                    xv[c] = xv[c] + eta * (dvv[c] - dot * xv[c]);
                    ss += xv[c] * xv[c];
                }
                ss += __shfl_xor_sync(0xffffffffu, ss, 1);
                ss += __shfl_xor_sync(0xffffffffu, ss, 2);
                float inv = 1.0f / fmaxf(sqrtf(ss), 1e-12f);
                #pragma unroll
                for (int c = 0; c < 16; c++) xv[c] *= inv;
                #pragma unroll
                for (int nt = 0; nt < 8; nt++) {
                    u32 off = xaddr(row, nt) + (u32)(tid4 * 4);
                    u32 lo; u32 hi = pack_h2(xv[nt*2], xv[nt*2+1], lo);
                    *(u32*)(smp + SM_XHI + off) = hi;
                    *(u32*)(smp + SM_XLO + off) = lo;
                }
                if (step == NSTEPS - 1) {
                    #pragma unroll
                    for (int nt = 0; nt < 8; nt++) {
                        const int col = nt*8 + tid4*2;
                        float2 wv = *(const float2*)&w_ro[col];
                        part += xv[nt*2] * wv.x + xv[nt*2+1] * wv.y;
                    }
                    if (write_x) {
                        #pragma unroll
                        for (int nt = 0; nt < 8; nt++) {
                            const int col = nt*8 + tid4*2;
                            *(float2*)&x_out[(size_t)b * NOSC * DDIM + row * DDIM + col] =
                                make_float2(xv[nt*2], xv[nt*2+1]);
                        }
                    }
                }
            }
        }
        __syncthreads();   // new X visible before next step's LDSM
    }

    // ---- readout reduction ----
    float* red = (float*)(smp + SM_RED);
    red[t] = part;
    __syncthreads();
    #pragma unroll
    for (int s = 128; s > 0; s >>= 1) {
        if (t < s) red[t] += red[t + s];
        __syncthreads();
    }
    if (t == 0) out[b] = red[0] / (float)NOSC + __ldg(b_ro);
}

extern "C" void kernel_launch(void* const* d_in, const int* in_sizes, int n_in,
                              void* d_out, int out_size) {
    const float* x    = (const float*)d_in[0];
    const float* eta  = (const float*)d_in[1];
    const float* W    = (const float*)d_in[2];
    const float* A    = (const float*)d_in[3];
    const float* h    = (const float*)d_in[4];
    const float* w_ro = (const float*)d_in[5];
    const float* b_ro = (const float*)d_in[6];

    const int B = in_sizes[0] / (NOSC * DDIM);
    float* out = (float*)d_out;
    int write_x = (out_size >= B + B * NOSC * DDIM) ? 1 : 0;
    float* x_out = out + B;

    cudaFuncSetAttribute(akorn_kernel,
                         cudaFuncAttributeMaxDynamicSharedMemorySize, SM_TOTAL);

    wprep_kernel<<<256, 256>>>(W);
    akorn_kernel<<<B, 256, SM_TOTAL>>>(x, eta, A, h, w_ro, b_ro,
                                       out, x_out, write_x);
}

// round 15
// speedup vs baseline: 9.7384x; 1.1436x over previous
#include <cuda_runtime.h>
#include <cuda_fp16.h>
#include <math.h>

typedef unsigned int u32;

#define NOSC 256
#define DDIM 64
#define NSTEPS 10

// smem byte offsets (total ~97 KB -> 2 CTAs/SM)
#define SM_XHI 0
#define SM_XLO 32768
#define SM_OHI 65536
#define SM_WB  73728          // 3 ring buffers x 8192B
#define SM_RED 98304
#define SM_TOTAL 99328

// W prepacked fp16 (hi only): 16 chunks (16 j-cols each, 8KB), warp-private regions:
// [pass(8192B)][warp(1024B)][plane(512B)][row*16B][j*2B]
__device__ __half g_Wpk[16 * 4096];
// h prepacked fp16 pairs in fragment-lane-major order: [warp][seg*2+half][lane][uint4]
__device__ uint4 g_hpk[8 * 8 * 32];

__global__ void wprep_kernel(const float* __restrict__ W) {
    int idx = blockIdx.x * 256 + threadIdx.x;   // 65536
    int i = idx >> 8, j = idx & 255;
    float v = W[i * 256 + j];
    __half hi = __float2half_rn(v);
    int p = j >> 4, plane = (j >> 3) & 1, jj = j & 7;
    int w = i >> 5, row = i & 31;
    // element offsets: pass 4096, warp 512, plane 256, row 8
    g_Wpk[p * 4096 + w * 512 + plane * 256 + row * 8 + jj] = hi;
}

__global__ void hprep_kernel(const float* __restrict__ h) {
    int idx = blockIdx.x * 256 + threadIdx.x;   // 8192 = 256 rows x 32 col-pairs
    int i = idx >> 5, ep = idx & 31, e = ep * 2;
    float v0 = h[i * DDIM + e], v1 = h[i * DDIM + e + 1];
    __half h0 = __float2half_rn(v0), h1 = __float2half_rn(v1);
    u32 val = (u32)__half_as_ushort(h0) | ((u32)__half_as_ushort(h1) << 16);
    int w = i >> 5, mt = (i >> 4) & 1, hh = (i >> 3) & 1, g = i & 7;
    int nt = e >> 3, half = nt >> 2, slot = nt & 3, tid4 = (e >> 1) & 3;
    int lane = g * 4 + tid4, seg = mt * 2 + hh;
    ((u32*)g_hpk)[(((w * 8) + seg * 2 + half) * 32 + lane) * 4 + slot] = val;
}

// ---------------- PTX helpers (baseline sm_80-level; compile for plain sm_100) ----------------
__device__ __forceinline__ u32 smem_u32(const void* p) {
    u32 a; asm("{ .reg .u64 t; cvta.to.shared.u64 t, %1; cvt.u32.u64 %0, t; }"
               : "=r"(a) : "l"(p));
    return a;
}
__device__ __forceinline__ void ldsm_x4(u32 addr, u32* r) {
    asm volatile("ldmatrix.sync.aligned.m8n8.x4.shared.b16 {%0,%1,%2,%3}, [%4];"
                 : "=r"(r[0]), "=r"(r[1]), "=r"(r[2]), "=r"(r[3]) : "r"(addr));
}
__device__ __forceinline__ void ldsm_x4t(u32 addr, u32* r) {
    asm volatile("ldmatrix.sync.aligned.m8n8.x4.trans.shared.b16 {%0,%1,%2,%3}, [%4];"
                 : "=r"(r[0]), "=r"(r[1]), "=r"(r[2]), "=r"(r[3]) : "r"(addr));
}
__device__ __forceinline__ void mma16816(float* c, const u32* a, u32 b0, u32 b1) {
    asm volatile("mma.sync.aligned.m16n8k16.row.col.f32.f16.f16.f32 "
                 "{%0,%1,%2,%3}, {%4,%5,%6,%7}, {%8,%9}, {%0,%1,%2,%3};"
                 : "+f"(c[0]), "+f"(c[1]), "+f"(c[2]), "+f"(c[3])
                 : "r"(a[0]), "r"(a[1]), "r"(a[2]), "r"(a[3]), "r"(b0), "r"(b1));
}
#define CP_ASYNC16(dst, src) \
    asm volatile("cp.async.cg.shared.global [%0], [%1], 16;" :: "r"(dst), "l"(src) : "memory")
#define CP_COMMIT()  asm volatile("cp.async.commit_group;" ::: "memory")
#define CP_WAIT1()   asm volatile("cp.async.wait_group 1;" ::: "memory")
#define CP_WAIT0()   asm volatile("cp.async.wait_group 0;" ::: "memory")

__device__ __forceinline__ u32 pack_h2(float v0, float v1, u32& lo_out) {
    __half h0 = __float2half_rn(v0), h1 = __float2half_rn(v1);
    __half l0 = __float2half_rn(v0 - __half2float(h0));
    __half l1 = __float2half_rn(v1 - __half2float(h1));
    lo_out = (u32)__half_as_ushort(l0) | ((u32)__half_as_ushort(l1) << 16);
    return (u32)__half_as_ushort(h0) | ((u32)__half_as_ushort(h1) << 16);
}
__device__ __forceinline__ float h2f_lo(u32 v) {
    return __half2float(__ushort_as_half((unsigned short)(v & 0xffffu)));
}
__device__ __forceinline__ float h2f_hi(u32 v) {
    return __half2float(__ushort_as_half((unsigned short)(v >> 16)));
}

// XOR chunk swizzle: 128B rows, 16B granules; granule' = granule ^ (row & 7)
__device__ __forceinline__ u32 xaddr(int row, int chunk) {
    return (u32)(row * 128 + ((chunk ^ (row & 7)) << 4));
}

__global__ __launch_bounds__(256, 2)
void akorn_kernel(const float* __restrict__ x_in,
                  const float* __restrict__ eta_p,
                  const float* __restrict__ A,
                  const float* __restrict__ w_ro,
                  const float* __restrict__ b_ro,
                  float* __restrict__ out,
                  float* __restrict__ x_out,
                  int write_x)
{
    extern __shared__ char smp[];
    const int b = blockIdx.x;
    const int t = threadIdx.x;
    const int wid = t >> 5, lane = t & 31;
    const int g = lane >> 2, tid4 = lane & 3;
    const int lr = lane & 15, lh = lane >> 4;
    const int l8 = lane & 7, q8 = lane >> 3;
    const int wbase = wid * 32;
    const u32 sb = smem_u32(smp);
    const float eta = __ldg(eta_p);

    // ---- initial x: load row t, normalize, store fp16 hi/lo (swizzled) ----
    {
        const float* xrow = x_in + (size_t)b * NOSC * DDIM + t * DDIM;
        float xr[DDIM]; float ss = 0.f;
        #pragma unroll
        for (int k = 0; k < 16; k++) {
            float4 v = __ldg((const float4*)&xrow[k * 4]);
            xr[4*k] = v.x; xr[4*k+1] = v.y; xr[4*k+2] = v.z; xr[4*k+3] = v.w;
            ss += v.x*v.x + v.y*v.y + v.z*v.z + v.w*v.w;
        }
        float inv = 1.0f / fmaxf(sqrtf(ss), 1e-12f);
        #pragma unroll
        for (int c = 0; c < DDIM; c++) xr[c] *= inv;
        #pragma unroll
        for (int q = 0; q < 8; q++) {
            u32 hs[4], ls[4];
            #pragma unroll
            for (int m = 0; m < 4; m++)
                hs[m] = pack_h2(xr[q*8 + 2*m], xr[q*8 + 2*m + 1], ls[m]);
            u32 a = xaddr(t, q);
            *(uint4*)(smp + SM_XHI + a) = make_uint4(hs[0], hs[1], hs[2], hs[3]);
            *(uint4*)(smp + SM_XLO + a) = make_uint4(ls[0], ls[1], ls[2], ls[3]);
        }
    }
    // ---- Omega = A - A^T, fp16 hi only (swizzled) ----
    if (t < DDIM) {
        int f = t;
        #pragma unroll 2
        for (int q = 0; q < 8; q++) {
            u32 hs[4];
            #pragma unroll
            for (int m = 0; m < 4; m++) {
                int e0 = q*8 + 2*m, e1 = e0 + 1;
                float v0 = __ldg(&A[f * DDIM + e0]) - __ldg(&A[e0 * DDIM + f]);
                float v1 = __ldg(&A[f * DDIM + e1]) - __ldg(&A[e1 * DDIM + f]);
                __half h0 = __float2half_rn(v0), h1 = __float2half_rn(v1);
                hs[m] = (u32)__half_as_ushort(h0) | ((u32)__half_as_ushort(h1) << 16);
            }
            *(uint4*)(smp + SM_OHI + xaddr(f, q)) = make_uint4(hs[0], hs[1], hs[2], hs[3]);
        }
    }
    __syncthreads();

    // Per-warp chunk copy: warp wid copies ONLY its own 1KB region of pass p into ring buf
    auto cp_chunk = [&](int p) {
        u32 sdst = sb + SM_WB + (u32)((p % 3) * 8192 + wid * 1024 + lane * 16);
        const char* src = ((const char*)g_Wpk) + (size_t)p * 8192 + wid * 1024 + lane * 16;
        CP_ASYNC16(sdst, src);
        CP_ASYNC16(sdst + 512, src + 512);
    };

    float part = 0.f;

    for (int step = 0; step < NSTEPS; step++) {
        float C[2][8][4];
        #pragma unroll
        for (int mt = 0; mt < 2; mt++)
            #pragma unroll
            for (int nt = 0; nt < 8; nt++)
                #pragma unroll
                for (int q = 0; q < 4; q++) C[mt][nt][q] = 0.f;

        cp_chunk(0); CP_COMMIT();
        cp_chunk(1); CP_COMMIT();

        // ---- Omega part: D += Xhi * Ohi (overlaps the 2-deep W prefetch) ----
        #pragma unroll
        for (int ks = 0; ks < 4; ks++) {
            const int f0 = ks * 16;
            u32 ah[2][4];
            #pragma unroll
            for (int mt = 0; mt < 2; mt++) {
                int arow = wbase + mt*16 + lr;
                ldsm_x4(sb + SM_XHI + xaddr(arow, (f0 >> 3) + lh), ah[mt]);
            }
            #pragma unroll
            for (int nt2 = 0; nt2 < 8; nt2 += 2) {
                u32 bo[4];
                ldsm_x4t(sb + SM_OHI + xaddr(f0 + ((q8 & 1) << 3) + l8, nt2 + (q8 >> 1)), bo);
                #pragma unroll
                for (int mt = 0; mt < 2; mt++) {
                    mma16816(C[mt][nt2],     ah[mt], bo[0], bo[1]);
                    mma16816(C[mt][nt2 + 1], ah[mt], bo[2], bo[3]);
                }
            }
        }

        // ---- W part: 16 warp-async passes of 16 j-cols, 3-buffer ring, depth-2 prefetch ----
        for (int p = 0; p < 16; p++) {
            if (p < 15) CP_WAIT1(); else CP_WAIT0();     // own region of chunk p resident
            if (p < 14) { cp_chunk(p + 2); CP_COMMIT(); }
            const u32 wb = sb + SM_WB + (u32)((p % 3) * 8192 + wid * 1024);
            u32 aw[2][4];
            #pragma unroll
            for (int mt = 0; mt < 2; mt++) {
                u32 ra = (u32)(lh * 512 + (mt*16 + lr) * 16);
                ldsm_x4(wb + ra, aw[mt]);
            }
            const int jb = p * 16;
            #pragma unroll
            for (int nt2 = 0; nt2 < 8; nt2 += 2) {
                u32 bx[4];
                ldsm_x4t(sb + SM_XHI + xaddr(jb + ((q8 & 1) << 3) + l8, nt2 + (q8 >> 1)), bx);
                #pragma unroll
                for (int mt = 0; mt < 2; mt++) {
                    mma16816(C[mt][nt2],     aw[mt], bx[0], bx[1]);
                    mma16816(C[mt][nt2 + 1], aw[mt], bx[2], bx[3]);
                }
            }
        }

        // ---- prefetch h fragments (global, read-only) BEFORE the barrier ----
        uint4 hreg[8];
        {
            const uint4* hp = g_hpk + (size_t)(wid * 8) * 32 + lane;
            #pragma unroll
            for (int k = 0; k < 8; k++) hreg[k] = __ldg(hp + k * 32);
        }
        __syncthreads();   // all warps' LDSM reads of X done before epilogue rewrites X

        // ---- epilogue in fragment layout (fp32 state = hi + lo) ----
        #pragma unroll
        for (int mt = 0; mt < 2; mt++) {
            #pragma unroll
            for (int hh = 0; hh < 2; hh++) {
                const int row = wbase + mt*16 + g + hh*8;
                const int seg = mt * 2 + hh;
                float xv[16], dvv[16];
                float dot = 0.f;
                #pragma unroll
                for (int nt = 0; nt < 8; nt++) {
                    const u32* hw = (const u32*)&hreg[seg * 2 + (nt >> 2)];
                    u32 hv = hw[nt & 3];
                    float d0 = C[mt][nt][hh*2 + 0] + h2f_lo(hv);
                    float d1 = C[mt][nt][hh*2 + 1] + h2f_hi(hv);
                    u32 off = xaddr(row, nt) + (u32)(tid4 * 4);
                    u32 vh = *(const u32*)(smp + SM_XHI + off);
                    u32 vl = *(const u32*)(smp + SM_XLO + off);
                    float x0 = h2f_lo(vh) + h2f_lo(vl);
                    float x1 = h2f_hi(vh) + h2f_hi(vl);
                    dot += x0 * d0 + x1 * d1;
                    xv[nt*2] = x0; xv[nt*2+1] = x1;
                    dvv[nt*2] = d0; dvv[nt*2+1] = d1;
                }
                dot += __shfl_xor_sync(0xffffffffu, dot, 1);
                dot += __shfl_xor_sync(0xffffffffu, dot, 2);
                float ss = 0.f;
                #pragma unroll
                for (int c = 0; c < 16; c++) {
                    xv[c] = xv[c] + eta * (dvv[c] - dot * xv[c]);
                    ss += xv[c] * xv[c];
                }
                ss += __shfl_xor_sync(0xffffffffu, ss, 1);
                ss += __shfl_xor_sync(0xffffffffu, ss, 2);
                float inv = 1.0f / fmaxf(sqrtf(ss), 1e-12f);
                #pragma unroll
                for (int c = 0; c < 16; c++) xv[c] *= inv;
                #pragma unroll
                for (int nt = 0; nt < 8; nt++) {
                    u32 off = xaddr(row, nt) + (u32)(tid4 * 4);
                    u32 lo; u32 hi = pack_h2(xv[nt*2], xv[nt*2+1], lo);
                    *(u32*)(smp + SM_XHI + off) = hi;
                    *(u32*)(smp + SM_XLO + off) = lo;
                }
                if (step == NSTEPS - 1) {
                    #pragma unroll
                    for (int nt = 0; nt < 8; nt++) {
                        const int col = nt*8 + tid4*2;
                        float2 wv = *(const float2*)&w_ro[col];
                        part += xv[nt*2] * wv.x + xv[nt*2+1] * wv.y;
                    }
                    if (write_x) {
                        #pragma unroll
                        for (int nt = 0; nt < 8; nt++) {
                            const int col = nt*8 + tid4*2;
                            *(float2*)&x_out[(size_t)b * NOSC * DDIM + row * DDIM + col] =
                                make_float2(xv[nt*2], xv[nt*2+1]);
                        }
                    }
                }
            }
        }
        __syncthreads();   // new X visible before next step's LDSM
    }

    // ---- readout reduction ----
    float* red = (float*)(smp + SM_RED);
    red[t] = part;
    __syncthreads();
    #pragma unroll
    for (int s = 128; s > 0; s >>= 1) {
        if (t < s) red[t] += red[t + s];
        __syncthreads();
    }
    if (t == 0) out[b] = red[0] / (float)NOSC + __ldg(b_ro);
}

extern "C" void kernel_launch(void* const* d_in, const int* in_sizes, int n_in,
                              void* d_out, int out_size) {
    const float* x    = (const float*)d_in[0];
    const float* eta  = (const float*)d_in[1];
    const float* W    = (const float*)d_in[2];
    const float* A    = (const float*)d_in[3];
    const float* h    = (const float*)d_in[4];
    const float* w_ro = (const float*)d_in[5];
    const float* b_ro = (const float*)d_in[6];

    const int B = in_sizes[0] / (NOSC * DDIM);
    float* out = (float*)d_out;
    int write_x = (out_size >= B + B * NOSC * DDIM) ? 1 : 0;
    float* x_out = out + B;

    cudaFuncSetAttribute(akorn_kernel,
                         cudaFuncAttributeMaxDynamicSharedMemorySize, SM_TOTAL);

    wprep_kernel<<<256, 256>>>(W);
    hprep_kernel<<<32, 256>>>(h);
    akorn_kernel<<<B, 256, SM_TOTAL>>>(x, eta, A, w_ro, b_ro,
                                       out, x_out, write_x);
}